// round 11
// baseline (speedup 1.0000x reference)
#include <cuda_runtime.h>
#include <math.h>

#define DINLINE __device__ __forceinline__

// ---------------- problem constants ----------------
#define Bb 8
#define Hh 128
#define Ww 128
#define Cc 96
#define Mm 192
#define SPEC (128*65)
#define INV_HW (1.0f/16384.0f)

// ---------------- device scratch ----------------
__device__ float  g_xpre[(size_t)Bb*Mm*Hh*Ww];     // reused in-place for xsp
__device__ float2 g_filt[(size_t)3*Mm*SPEC];       // resized filters (BR h order)
__device__ float2 g_tmp[(size_t)48*65*Mm];         // separable-resize intermediate
__device__ float  g_r[Bb*3*Mm];
__device__ float  g_stats[Bb*144];
// tf32-split weights: rows 0..191 = w1, rows 192..239 = spw
__device__ float  g_w1hi[240*96], g_w1lo[240*96];
__device__ float  g_w2hi[96*192], g_w2lo[96*192];

extern __shared__ __align__(16) char SMEM[];

// ---------------- helpers ----------------
DINLINE int br7(int p){ return (int)(__brev((unsigned)p)>>25); }
DINLINE float2 cmulf(float2 a, float2 b){ return make_float2(a.x*b.x - a.y*b.y, a.x*b.y + a.y*b.x); }
DINLINE float2 f2add(float2 a,float2 b){ return make_float2(a.x+b.x, a.y+b.y); }
DINLINE float2 f2sub(float2 a,float2 b){ return make_float2(a.x-b.x, a.y-b.y); }
DINLINE float2 shflx(float2 v,int m){
    v.x = __shfl_xor_sync(0xffffffffu, v.x, m);
    v.y = __shfl_xor_sync(0xffffffffu, v.y, m);
    return v;
}
// tf32 helpers
DINLINE unsigned f2tf(float x){ unsigned r; asm("cvt.rna.tf32.f32 %0,%1;":"=r"(r):"f"(x)); return r; }
DINLINE void tfsplit(float x, unsigned& hi, unsigned& lo){
    hi = f2tf(x);
    lo = f2tf(x - __uint_as_float(hi));
}
DINLINE void mma8(float c[4], const unsigned a[4], unsigned b0, unsigned b1){
    asm("mma.sync.aligned.m16n8k8.row.col.f32.tf32.tf32.f32 "
        "{%0,%1,%2,%3},{%4,%5,%6,%7},{%8,%9},{%0,%1,%2,%3};"
        : "+f"(c[0]),"+f"(c[1]),"+f"(c[2]),"+f"(c[3])
        : "r"(a[0]),"r"(a[1]),"r"(a[2]),"r"(a[3]),"r"(b0),"r"(b1));
}

// Forward DIF 128-pt FFT
DINLINE void fft128_dif(float2 z[4], const float2* tw, int lane){
    #pragma unroll
    for(int j=0;j<2;j++){
        int k=j*32+lane;
        float2 u=z[j], v=z[j+2];
        z[j]=f2add(u,v);
        z[j+2]=cmulf(f2sub(u,v), tw[k]);
    }
    {
        float2 w=tw[2*lane];
        float2 u=z[0],v=z[1];
        z[0]=f2add(u,v); z[1]=cmulf(f2sub(u,v),w);
        u=z[2]; v=z[3];
        z[2]=f2add(u,v); z[3]=cmulf(f2sub(u,v),w);
    }
    #pragma unroll
    for(int d=16; d>=1; d>>=1){
        int k=lane&(d-1);
        float2 w=tw[k*(64/d)];
        bool up=(lane&d)!=0;
        #pragma unroll
        for(int j=0;j<4;j++){
            float2 o=shflx(z[j],d);
            float2 r;
            if(up) r=cmulf(make_float2(o.x - z[j].x, o.y - z[j].y), w);
            else   r=make_float2(z[j].x+o.x, z[j].y+o.y);
            z[j]=r;
        }
    }
}

// DIT 128-pt FFT
template<bool CONJ>
DINLINE void fft128_dit(float2 z[4], const float2* tw, int lane){
    #pragma unroll
    for(int d=1; d<=16; d<<=1){
        int k=lane&(d-1);
        float2 w=tw[k*(64/d)];
        if(CONJ) w.y=-w.y;
        bool up=(lane&d)!=0;
        #pragma unroll
        for(int j=0;j<4;j++){
            float2 o=shflx(z[j],d);
            float2 r;
            if(up){
                float2 t=cmulf(w, z[j]);
                r=make_float2(o.x-t.x, o.y-t.y);
            } else {
                float2 t=cmulf(w, o);
                r=make_float2(z[j].x+t.x, z[j].y+t.y);
            }
            z[j]=r;
        }
    }
    {
        float2 w=tw[2*lane]; if(CONJ) w.y=-w.y;
        float2 t=cmulf(w,z[1]); float2 u=z[0];
        z[0]=f2add(u,t); z[1]=f2sub(u,t);
        t=cmulf(w,z[3]); u=z[2];
        z[2]=f2add(u,t); z[3]=f2sub(u,t);
    }
    #pragma unroll
    for(int j=0;j<2;j++){
        int k=j*32+lane;
        float2 w=tw[k]; if(CONJ) w.y=-w.y;
        float2 t=cmulf(w,z[j+2]); float2 u=z[j];
        z[j]=f2add(u,t);
        z[j+2]=f2sub(u,t);
    }
}

// ---------------- bicubic resize taps ----------------
DINLINE double cubicw(double t){
    t = fabs(t);
    const double a = -0.75;
    if(t <= 1.0) return ((a+2.0)*t - (a+3.0))*t*t + 1.0;
    if(t <  2.0) return a*(((t-5.0)*t+8.0)*t-4.0);
    return 0.0;
}
DINLINE void taps4(int j, int oldn, int newn, int* idx, float* wt){
    double s = (newn > 1) ? (double)j * (double)(oldn-1) / (double)(newn-1) : 0.0;
    int f = (int)floor(s);
    #pragma unroll
    for(int k=0;k<4;k++){
        int kk = f + k - 1;
        idx[k] = min(max(kk, 0), oldn-1);
        wt[k]  = (float)cubicw(s - (double)kk);
    }
}

__constant__ int c_SH[3]={16,8,24};
__constant__ int c_SW[3]={9,4,13};
__constant__ int c_RB[3]={0,16,24};

// ---------------- k_prep (also zeroes g_stats) ----------------
__global__ void __launch_bounds__(256) k_prep(const float* __restrict__ w1,
                                              const float* __restrict__ spw,
                                              const float* __restrict__ w2){
    int tid=blockIdx.x*256+threadIdx.x;
    if(blockIdx.x==0){
        for(int i=threadIdx.x;i<Bb*144;i+=256) g_stats[i]=0.f;
    }
    for(int i=tid;i<240*96;i+=256*32){
        int n=i/96, k=i%96;
        float w = (n<192)? w1[n*96+k] : spw[(n-192)*96+k];
        unsigned hi,lo; tfsplit(w,hi,lo);
        g_w1hi[i]=__uint_as_float(hi);
        g_w1lo[i]=__uint_as_float(lo);
    }
    for(int i=tid;i<96*192;i+=256*32){
        float w = w2[i];
        unsigned hi,lo; tfsplit(w,hi,lo);
        g_w2hi[i]=__uint_as_float(hi);
        g_w2lo[i]=__uint_as_float(lo);
    }
}

// ---------------- k_filt1 ----------------
__global__ void __launch_bounds__(256) k_filt1(const float* __restrict__ cw0,
                                               const float* __restrict__ cw1,
                                               const float* __restrict__ cw2){
    __shared__ int   widx[65][4];
    __shared__ float wwt [65][4];
    __shared__ float2 rowb[13*Mm];
    int r = blockIdx.x;
    int s = (r<16)?0:((r<24)?1:2);
    int ih = r - c_RB[s];
    int ow = c_SW[s];
    const float* cws = (s==0)?cw0:((s==1)?cw1:cw2);
    int tid=threadIdx.x;
    if(tid<65) taps4(tid, ow, 65, widx[tid], wwt[tid]);
    const float2* src = (const float2*)(cws) + (size_t)ih*ow*Mm;
    for(int i=tid;i<ow*Mm;i+=256) rowb[i]=src[i];
    __syncthreads();
    float2* dst = g_tmp + (size_t)r*65*Mm;
    for(int e=tid;e<65*Mm;e+=256){
        int w=e/Mm, m=e%Mm;
        float ax=0.f, ay=0.f;
        #pragma unroll
        for(int a=0;a<4;a++){
            float wg=wwt[w][a];
            float2 v=rowb[widx[w][a]*Mm+m];
            ax+=wg*v.x; ay+=wg*v.y;
        }
        dst[e]=make_float2(ax,ay);
    }
}

// ---------------- k_filt2 ----------------
__global__ void __launch_bounds__(128) k_filt2(){
    __shared__ int   hidx[4];
    __shared__ float hwt [4];
    __shared__ float2 tile[48*65];
    int bid=blockIdx.x;
    int s  = bid/512;
    int rem= bid%512;
    int hq = rem/4;
    int m0 = (rem%4)*48;
    int tid=threadIdx.x;
    if(tid==0){
        int id[4]; float wt[4];
        taps4(hq, c_SH[s], 128, id, wt);
        #pragma unroll
        for(int a=0;a<4;a++){ hidx[a]=id[a]; hwt[a]=wt[a]; }
    }
    __syncthreads();
    const float2* base = g_tmp + (size_t)c_RB[s]*65*Mm;
    for(int e=tid;e<65*48;e+=128){
        int w=e/48, mm=e%48;
        int m=m0+mm;
        float ax=0.f, ay=0.f;
        #pragma unroll
        for(int a=0;a<4;a++){
            float2 v=base[(size_t)hidx[a]*65*Mm + w*Mm + m];
            ax+=hwt[a]*v.x; ay+=hwt[a]*v.y;
        }
        tile[mm*65+w]=make_float2(ax,ay);
    }
    __syncthreads();
    int hb=br7(hq);
    for(int e=tid;e<48*65;e+=128){
        int mm=e/65, w=e%65;
        g_filt[(size_t)(s*Mm+m0+mm)*SPEC + hb*65 + w]=tile[mm*65+w];
    }
}

// ---------------- k_pw1: tf32 MMA pwconv1+Soa + routing stats ----------------
#define P1_XS  0
#define P1_WH  (P1_XS+12800)
#define P1_WL  (P1_WH+12480)
#define P1_SB  (P1_WL+12480)
#define P1_BNP (P1_SB+6336)
#define P1_RED (P1_BNP+96)
#define P1_TOT (P1_RED+192)
__global__ void __launch_bounds__(256) k_pw1(const float* __restrict__ x,
                                             const float* __restrict__ s1,
                                             const float* __restrict__ b1,
                                             const float* __restrict__ bng,
                                             const float* __restrict__ bnb,
                                             const float* __restrict__ bnm,
                                             const float* __restrict__ bnv){
    float* S=(float*)SMEM;
    float* xs  = S+P1_XS;      // [128][100]
    float* wsh = S+P1_WH;      // [240][52]
    float* wsl = S+P1_WL;
    float* sb  = S+P1_SB;      // [48][132]
    float* bnp = S+P1_BNP;
    float* red = S+P1_RED;
    int tid=threadIdx.x;
    int b=blockIdx.y, pix0=blockIdx.x*128;
    const float* xb = x + ((size_t)b*16384 + pix0)*96;
    for(int i=tid;i<128*96;i+=256){ int p=i/96,c=i%96; xs[p*100+c]=xb[i]; }
    if(tid<48){
        float sc=rsqrtf(bnv[tid]+1e-5f)*bng[tid];
        bnp[tid]=sc;
        bnp[48+tid]=bnb[tid]-bnm[tid]*sc;
    }
    int warp=tid>>5, lane=tid&31;
    int gid=lane>>2, tig=lane&3;
    int pr0=warp*16;
    float C[30][4];
    #pragma unroll
    for(int n=0;n<30;n++){ C[n][0]=0.f;C[n][1]=0.f;C[n][2]=0.f;C[n][3]=0.f; }
    #pragma unroll 1
    for(int kh=0;kh<2;kh++){
        __syncthreads();
        for(int i=tid;i<240*48;i+=256){
            int n=i/48, kk=i%48;
            wsh[n*52+kk]=g_w1hi[n*96 + kh*48 + kk];
            wsl[n*52+kk]=g_w1lo[n*96 + kh*48 + kk];
        }
        __syncthreads();
        unsigned ah[6][4], al[6][4];
        #pragma unroll
        for(int kt=0;kt<6;kt++){
            int k0=kh*48+kt*8;
            float r0=xs[(pr0+gid  )*100 + k0+tig];
            float r1=xs[(pr0+gid+8)*100 + k0+tig];
            float r2=xs[(pr0+gid  )*100 + k0+tig+4];
            float r3=xs[(pr0+gid+8)*100 + k0+tig+4];
            tfsplit(r0,ah[kt][0],al[kt][0]);
            tfsplit(r1,ah[kt][1],al[kt][1]);
            tfsplit(r2,ah[kt][2],al[kt][2]);
            tfsplit(r3,ah[kt][3],al[kt][3]);
        }
        // fused: 4 LDS per (n,kt), 3 MMAs; full unroll keeps C in regs,
        // ptxas interleaves across n to hide accumulator RAW chains
        #pragma unroll
        for(int kt=0;kt<6;kt++){
            int kk=kt*8;
            #pragma unroll
            for(int n=0;n<30;n++){
                int nrow=(n*8+gid)*52 + kk;
                unsigned b0h=__float_as_uint(wsh[nrow+tig]);
                unsigned b1h=__float_as_uint(wsh[nrow+tig+4]);
                unsigned b0l=__float_as_uint(wsl[nrow+tig]);
                unsigned b1l=__float_as_uint(wsl[nrow+tig+4]);
                mma8(C[n], ah[kt], b0h, b1h);
                mma8(C[n], al[kt], b0h, b1h);
                mma8(C[n], ah[kt], b0l, b1l);
            }
        }
    }
    // gctx sums from xs BEFORE region reuse
    float gsum=0.f;
    if(tid<96){
        #pragma unroll 4
        for(int p=0;p<128;p++) gsum+=xs[p*100+tid];
    }
    // sctx rows -> sb
    #pragma unroll
    for(int n=24;n<30;n++){
        int sc=(n-24)*8+2*tig;
        int p=pr0+gid;
        sb[sc*132+p]      =C[n][0];
        sb[(sc+1)*132+p]  =C[n][1];
        sb[sc*132+p+8]    =C[n][2];
        sb[(sc+1)*132+p+8]=C[n][3];
    }
    float scb=*s1, bib=*b1;
    __syncthreads();
    // stage m<192 outputs (Soa applied) into outs[192][132]
    float* outs = S;   // 192*132 = 25344 floats < 37760
    #pragma unroll
    for(int n=0;n<24;n++){
        int mch=n*8+2*tig;
        int p=pr0+gid;
        float v0=fmaxf(C[n][0],0.f), v1=fmaxf(C[n][1],0.f);
        float v2=fmaxf(C[n][2],0.f), v3=fmaxf(C[n][3],0.f);
        outs[mch*132+p]      =scb*v0*v0+bib;
        outs[(mch+1)*132+p]  =scb*v1*v1+bib;
        outs[mch*132+p+8]    =scb*v2*v2+bib;
        outs[(mch+1)*132+p+8]=scb*v3*v3+bib;
    }
    if(tid<96) atomicAdd(&g_stats[b*144+tid], gsum);
    __syncthreads();
    // coalesced write to g_xpre
    float* op = g_xpre + (size_t)b*Mm*16384 + pix0;
    for(int i=tid;i<192*128;i+=256){
        int mm=i>>7, p=i&127;
        op[(size_t)mm*16384+p]=outs[mm*132+p];
    }
    // sctx reduce
    if(tid<192){
        int sc=tid>>2, q=tid&3;
        float scale=bnp[sc], shift=bnp[48+sc];
        float s=0.f;
        #pragma unroll 4
        for(int p=q*32;p<q*32+32;p++) s+=fmaxf(sb[sc*132+p]*scale+shift,0.f);
        red[sc*4+q]=s;
    }
    __syncthreads();
    if(tid<48) atomicAdd(&g_stats[b*144+96+tid], red[4*tid]+red[4*tid+1]+red[4*tid+2]+red[4*tid+3]);
}

// ---------------- k_mlp ----------------
#define MLP_SF   0
#define MLP_FC1  (8*145)
#define MLP_HM   (MLP_FC1+36*145)
#define MLP_FC2  (MLP_HM+8*37)
#define MLP_TOT  (MLP_FC2+576*37)
__global__ void __launch_bounds__(512) k_mlp(const float* __restrict__ fc1,
                                             const float* __restrict__ fc2,
                                             const float* __restrict__ msc,
                                             const float* __restrict__ mbi){
    float* S=(float*)SMEM;
    float* sf  = S+MLP_SF;
    float* f1s = S+MLP_FC1;
    float* hm  = S+MLP_HM;
    float* f2s = S+MLP_FC2;
    int tid=threadIdx.x;
    for(int i=tid;i<8*144;i+=512){ int b=i/144,k=i%144; sf[b*145+k]=g_stats[i]*(1.f/16384.f); }
    for(int i=tid;i<36*144;i+=512){ int j=i/144,k=i%144; f1s[j*145+k]=fc1[i]; }
    for(int i=tid;i<576*36;i+=512){ int j=i/36,k=i%36; f2s[j*37+k]=fc2[i]; }
    __syncthreads();
    if(tid<288){
        int b=tid/36, j=tid%36;
        float a=0.f;
        #pragma unroll 8
        for(int k=0;k<144;k++) a+=sf[b*145+k]*f1s[j*145+k];
        float r=fmaxf(a,0.f);
        hm[b*37+j]=(*msc)*r*r + (*mbi);
    }
    __syncthreads();
    for(int idx=tid; idx<8*Mm; idx+=512){
        int b=idx/Mm, m=idx%Mm;
        float lg[3];
        #pragma unroll
        for(int s=0;s<3;s++){
            float a=0.f;
            const float* f2=f2s+(size_t)(s*Mm+m)*37;
            #pragma unroll
            for(int k=0;k<36;k++) a+=hm[b*37+k]*f2[k];
            lg[s]=a;
        }
        float mx=fmaxf(lg[0],fmaxf(lg[1],lg[2]));
        float e0=expf(lg[0]-mx), e1=expf(lg[1]-mx), e2=expf(lg[2]-mx);
        float inv=1.f/(e0+e1+e2);
        g_r[(b*3+0)*Mm+m]=e0*inv;
        g_r[(b*3+1)*Mm+m]=e1*inv;
        g_r[(b*3+2)*Mm+m]=e2*inv;
    }
}

// ---------------- k_fft (512 thr) ----------------
__global__ void __launch_bounds__(512) k_fft(){
    float2* sh=(float2*)SMEM;
    float2* sm = sh;
    float2* tmpAll = sh + SPEC;
    float2* tw = sh + SPEC + 2048;
    int tid=threadIdx.x, lane=tid&31, wid=tid>>5;
    int bm=blockIdx.x;
    int b=bm/Mm, m=bm%Mm;
    float* plane = g_xpre + (size_t)bm*16384;
    if(tid<64){
        float s,c;
        sincospif((float)tid*(1.0f/64.0f), &s, &c);
        tw[tid]=make_float2(c,-s);
    }
    __syncthreads();
    float2* tmp = tmpAll + wid*128;
    // Phase A: forward row rFFTs — coalesced global loads, bit-reversed LDS gather
    for(int pr=wid; pr<64; pr+=16){
        int ra=2*pr, rb=ra+1;
        #pragma unroll
        for(int t=0;t<4;t++){
            int idx=t*32+lane;
            tmp[idx]=make_float2(plane[ra*128+idx], plane[rb*128+idx]);
        }
        __syncwarp();
        float2 z[4];
        #pragma unroll
        for(int j=0;j<4;j++) z[j]=tmp[br7(j*32+lane)];
        fft128_dit<false>(z,tw,lane);
        __syncwarp();
        #pragma unroll
        for(int j=0;j<4;j++) tmp[j*32+lane]=z[j];
        __syncwarp();
        #pragma unroll
        for(int t=0;t<2;t++){
            int k=t*32+lane;
            float2 Zk=tmp[k], Zc=tmp[(128-k)&127];
            sm[ra*65+k]=make_float2(0.5f*(Zk.x+Zc.x), 0.5f*(Zk.y-Zc.y));
            sm[rb*65+k]=make_float2(0.5f*(Zk.y+Zc.y), 0.5f*(Zc.x-Zk.x));
        }
        if(lane==0){
            float2 Zk=tmp[64];
            sm[ra*65+64]=make_float2(Zk.x,0.f);
            sm[rb*65+64]=make_float2(Zk.y,0.f);
        }
        __syncwarp();
    }
    __syncthreads();
    for(int col=wid; col<65; col+=16){
        float2 z[4];
        #pragma unroll
        for(int j=0;j<4;j++) z[j]=sm[(j*32+lane)*65+col];
        fft128_dif(z,tw,lane);
        #pragma unroll
        for(int j=0;j<4;j++) sm[(j*32+lane)*65+col]=z[j];
    }
    __syncthreads();
    {
        float r0=g_r[(b*3+0)*Mm+m], r1=g_r[(b*3+1)*Mm+m], r2=g_r[(b*3+2)*Mm+m];
        const float2* f0=g_filt + (size_t)(0*Mm+m)*SPEC;
        const float2* f1=g_filt + (size_t)(1*Mm+m)*SPEC;
        const float2* f2=g_filt + (size_t)(2*Mm+m)*SPEC;
        for(int e=tid;e<SPEC;e+=512){
            float2 a=f0[e], bb=f1[e], c=f2[e];
            float2 comb=make_float2(a.x*r0+bb.x*r1+c.x*r2, a.y*r0+bb.y*r1+c.y*r2);
            sm[e]=cmulf(sm[e],comb);
        }
    }
    __syncthreads();
    for(int col=wid; col<65; col+=16){
        float2 z[4];
        #pragma unroll
        for(int j=0;j<4;j++) z[j]=sm[(j*32+lane)*65+col];
        fft128_dit<true>(z,tw,lane);
        #pragma unroll
        for(int j=0;j<4;j++) sm[(j*32+lane)*65+col]=z[j];
    }
    __syncthreads();
    for(int pr=wid; pr<64; pr+=16){
        int ra=2*pr, rb=ra+1;
        float2 z[4];
        #pragma unroll
        for(int j=0;j<4;j++){
            int p=j*32+lane, k=br7(p);
            float2 zz;
            if(k<=64){
                float2 a=sm[ra*65+k], bb=sm[rb*65+k];
                if(k==0||k==64){ a.y=0.f; bb.y=0.f; }
                zz=make_float2(a.x-bb.y, a.y+bb.x);
            } else {
                int kk=128-k;
                float2 a=sm[ra*65+kk], bb=sm[rb*65+kk];
                zz=make_float2(a.x+bb.y, bb.x-a.y);
            }
            z[j]=zz;
        }
        fft128_dit<true>(z,tw,lane);
        #pragma unroll
        for(int j=0;j<4;j++){
            int p=j*32+lane;
            plane[ra*128+p]=z[j].x*INV_HW;
            plane[rb*128+p]=z[j].y*INV_HW;
        }
    }
}

// ---------------- k_pw2: tf32 MMA pwconv2 (fused passes) ----------------
#define P2_AS  0
#define P2_WH  (P2_AS+25088)
#define P2_WL  (P2_WH+9600)
#define P2_TOT (P2_WL+9600)
__global__ void __launch_bounds__(256) k_pw2(float* __restrict__ out){
    float* S=(float*)SMEM;
    float* As = S+P2_AS;      // [128][196] k-major
    float* wh = S+P2_WH;
    float* wl = S+P2_WL;
    int tid=threadIdx.x;
    int b=blockIdx.y, pix0=blockIdx.x*128;
    const float* ap = g_xpre + (size_t)b*Mm*16384 + pix0;
    for(int i=tid;i<192*128;i+=256){
        int mm=i>>7, p=i&127;
        As[p*196+mm]=ap[(size_t)mm*16384+p];
    }
    int warp=tid>>5, lane=tid&31;
    int gid=lane>>2, tig=lane&3;
    int pr0=warp*16;
    float C[12][4];
    #pragma unroll
    for(int n=0;n<12;n++){ C[n][0]=0.f;C[n][1]=0.f;C[n][2]=0.f;C[n][3]=0.f; }
    #pragma unroll 1
    for(int kh=0;kh<2;kh++){
        __syncthreads();
        for(int i=tid;i<96*96;i+=256){
            int c=i/96, kk=i%96;
            wh[c*100+kk]=g_w2hi[c*192 + kh*96 + kk];
            wl[c*100+kk]=g_w2lo[c*192 + kh*96 + kk];
        }
        __syncthreads();
        unsigned ah[12][4], al[12][4];
        #pragma unroll
        for(int kt=0;kt<12;kt++){
            int k0=kh*96+kt*8;
            float r0=As[(pr0+gid  )*196 + k0+tig];
            float r1=As[(pr0+gid+8)*196 + k0+tig];
            float r2=As[(pr0+gid  )*196 + k0+tig+4];
            float r3=As[(pr0+gid+8)*196 + k0+tig+4];
            tfsplit(r0,ah[kt][0],al[kt][0]);
            tfsplit(r1,ah[kt][1],al[kt][1]);
            tfsplit(r2,ah[kt][2],al[kt][2]);
            tfsplit(r3,ah[kt][3],al[kt][3]);
        }
        #pragma unroll
        for(int kt=0;kt<12;kt++){
            int kk=kt*8;
            #pragma unroll
            for(int n=0;n<12;n++){
                int nrow=(n*8+gid)*100 + kk;
                unsigned b0h=__float_as_uint(wh[nrow+tig]);
                unsigned b1h=__float_as_uint(wh[nrow+tig+4]);
                unsigned b0l=__float_as_uint(wl[nrow+tig]);
                unsigned b1l=__float_as_uint(wl[nrow+tig+4]);
                mma8(C[n], ah[kt], b0h, b1h);
                mma8(C[n], al[kt], b0h, b1h);
                mma8(C[n], ah[kt], b0l, b1l);
            }
        }
    }
    __syncthreads();
    // stage into outs[128][100] then coalesced write
    float* outs=S;
    #pragma unroll
    for(int n=0;n<12;n++){
        int c0=n*8+2*tig;
        int p=pr0+gid;
        outs[p*100+c0]      =C[n][0];
        outs[p*100+c0+1]    =C[n][1];
        outs[(p+8)*100+c0]  =C[n][2];
        outs[(p+8)*100+c0+1]=C[n][3];
    }
    __syncthreads();
    float* op = out + ((size_t)b*16384 + pix0)*96;
    for(int i=tid;i<128*96;i+=256){
        int p=i/96, c=i%96;
        op[i]=outs[p*100+c];
    }
}

// ---------------- launch ----------------
extern "C" void kernel_launch(void* const* d_in, const int* in_sizes, int n_in,
                              void* d_out, int out_size){
    (void)in_sizes; (void)n_in; (void)out_size;
    const float* x   =(const float*)d_in[0];
    const float* w1  =(const float*)d_in[1];
    const float* s1  =(const float*)d_in[2];
    const float* b1  =(const float*)d_in[3];
    const float* cw0 =(const float*)d_in[4];
    const float* cw1 =(const float*)d_in[5];
    const float* cw2 =(const float*)d_in[6];
    const float* spw =(const float*)d_in[7];
    const float* bng =(const float*)d_in[8];
    const float* bnb =(const float*)d_in[9];
    const float* bnm =(const float*)d_in[10];
    const float* bnv =(const float*)d_in[11];
    const float* fc1 =(const float*)d_in[12];
    const float* msc =(const float*)d_in[13];
    const float* mbi =(const float*)d_in[14];
    const float* fc2 =(const float*)d_in[15];
    const float* w2  =(const float*)d_in[16];
    float* out=(float*)d_out;

    const int SM_PW1 = P1_TOT*4;
    const int SM_FFT = (SPEC+2048+64)*8;
    const int SM_PW2 = P2_TOT*4;
    const int SM_MLP = MLP_TOT*4;

    cudaFuncSetAttribute(k_pw1, cudaFuncAttributeMaxDynamicSharedMemorySize, SM_PW1);
    cudaFuncSetAttribute(k_fft, cudaFuncAttributeMaxDynamicSharedMemorySize, SM_FFT);
    cudaFuncSetAttribute(k_pw2, cudaFuncAttributeMaxDynamicSharedMemorySize, SM_PW2);
    cudaFuncSetAttribute(k_mlp, cudaFuncAttributeMaxDynamicSharedMemorySize, SM_MLP);

    k_prep<<<32, 256>>>(w1, spw, w2);
    k_filt1<<<48, 256>>>(cw0, cw1, cw2);
    k_filt2<<<3*128*4, 128>>>();
    k_pw1<<<dim3(128,Bb), 256, SM_PW1>>>(x, s1, b1, bng, bnb, bnm, bnv);
    k_mlp<<<1, 512, SM_MLP>>>(fc1, fc2, msc, mbi);
    k_fft<<<Bb*Mm, 512, SM_FFT>>>();
    k_pw2<<<dim3(128,Bb), 256, SM_PW2>>>(out);
}

// round 12
// speedup vs baseline: 1.0022x; 1.0022x over previous
#include <cuda_runtime.h>
#include <math.h>

#define DINLINE __device__ __forceinline__

// ---------------- problem constants ----------------
#define Bb 8
#define Hh 128
#define Ww 128
#define Cc 96
#define Mm 192
#define SPEC (128*65)
#define INV_HW (1.0f/16384.0f)

// ---------------- device scratch ----------------
__device__ float  g_xpre[(size_t)Bb*Mm*Hh*Ww];     // reused in-place for xsp
__device__ float2 g_filt[(size_t)3*Mm*SPEC];       // resized filters (BR h order)
__device__ float2 g_tmp[(size_t)48*65*Mm];         // separable-resize intermediate
__device__ float  g_r[Bb*3*Mm];
__device__ float  g_stats[Bb*144];
// tf32-split weights: rows 0..191 = w1, rows 192..239 = spw
__device__ float  g_w1hi[240*96], g_w1lo[240*96];
__device__ float  g_w2hi[96*192], g_w2lo[96*192];

extern __shared__ __align__(16) char SMEM[];

// ---------------- helpers ----------------
DINLINE int br7(int p){ return (int)(__brev((unsigned)p)>>25); }
DINLINE float2 cmulf(float2 a, float2 b){ return make_float2(a.x*b.x - a.y*b.y, a.x*b.y + a.y*b.x); }
DINLINE float2 f2add(float2 a,float2 b){ return make_float2(a.x+b.x, a.y+b.y); }
DINLINE float2 f2sub(float2 a,float2 b){ return make_float2(a.x-b.x, a.y-b.y); }
DINLINE float2 shflx(float2 v,int m){
    v.x = __shfl_xor_sync(0xffffffffu, v.x, m);
    v.y = __shfl_xor_sync(0xffffffffu, v.y, m);
    return v;
}
// tf32 helpers
DINLINE unsigned f2tf(float x){ unsigned r; asm("cvt.rna.tf32.f32 %0,%1;":"=r"(r):"f"(x)); return r; }
DINLINE void tfsplit(float x, unsigned& hi, unsigned& lo){
    hi = f2tf(x);
    lo = f2tf(x - __uint_as_float(hi));
}
DINLINE void mma8(float c[4], const unsigned a[4], unsigned b0, unsigned b1){
    asm("mma.sync.aligned.m16n8k8.row.col.f32.tf32.tf32.f32 "
        "{%0,%1,%2,%3},{%4,%5,%6,%7},{%8,%9},{%0,%1,%2,%3};"
        : "+f"(c[0]),"+f"(c[1]),"+f"(c[2]),"+f"(c[3])
        : "r"(a[0]),"r"(a[1]),"r"(a[2]),"r"(a[3]),"r"(b0),"r"(b1));
}

// Forward DIF 128-pt FFT
DINLINE void fft128_dif(float2 z[4], const float2* tw, int lane){
    #pragma unroll
    for(int j=0;j<2;j++){
        int k=j*32+lane;
        float2 u=z[j], v=z[j+2];
        z[j]=f2add(u,v);
        z[j+2]=cmulf(f2sub(u,v), tw[k]);
    }
    {
        float2 w=tw[2*lane];
        float2 u=z[0],v=z[1];
        z[0]=f2add(u,v); z[1]=cmulf(f2sub(u,v),w);
        u=z[2]; v=z[3];
        z[2]=f2add(u,v); z[3]=cmulf(f2sub(u,v),w);
    }
    #pragma unroll
    for(int d=16; d>=1; d>>=1){
        int k=lane&(d-1);
        float2 w=tw[k*(64/d)];
        bool up=(lane&d)!=0;
        #pragma unroll
        for(int j=0;j<4;j++){
            float2 o=shflx(z[j],d);
            float2 r;
            if(up) r=cmulf(make_float2(o.x - z[j].x, o.y - z[j].y), w);
            else   r=make_float2(z[j].x+o.x, z[j].y+o.y);
            z[j]=r;
        }
    }
}

// DIT 128-pt FFT
template<bool CONJ>
DINLINE void fft128_dit(float2 z[4], const float2* tw, int lane){
    #pragma unroll
    for(int d=1; d<=16; d<<=1){
        int k=lane&(d-1);
        float2 w=tw[k*(64/d)];
        if(CONJ) w.y=-w.y;
        bool up=(lane&d)!=0;
        #pragma unroll
        for(int j=0;j<4;j++){
            float2 o=shflx(z[j],d);
            float2 r;
            if(up){
                float2 t=cmulf(w, z[j]);
                r=make_float2(o.x-t.x, o.y-t.y);
            } else {
                float2 t=cmulf(w, o);
                r=make_float2(z[j].x+t.x, z[j].y+t.y);
            }
            z[j]=r;
        }
    }
    {
        float2 w=tw[2*lane]; if(CONJ) w.y=-w.y;
        float2 t=cmulf(w,z[1]); float2 u=z[0];
        z[0]=f2add(u,t); z[1]=f2sub(u,t);
        t=cmulf(w,z[3]); u=z[2];
        z[2]=f2add(u,t); z[3]=f2sub(u,t);
    }
    #pragma unroll
    for(int j=0;j<2;j++){
        int k=j*32+lane;
        float2 w=tw[k]; if(CONJ) w.y=-w.y;
        float2 t=cmulf(w,z[j+2]); float2 u=z[j];
        z[j]=f2add(u,t);
        z[j+2]=f2sub(u,t);
    }
}

// ---------------- bicubic resize taps ----------------
DINLINE double cubicw(double t){
    t = fabs(t);
    const double a = -0.75;
    if(t <= 1.0) return ((a+2.0)*t - (a+3.0))*t*t + 1.0;
    if(t <  2.0) return a*(((t-5.0)*t+8.0)*t-4.0);
    return 0.0;
}
DINLINE void taps4(int j, int oldn, int newn, int* idx, float* wt){
    double s = (newn > 1) ? (double)j * (double)(oldn-1) / (double)(newn-1) : 0.0;
    int f = (int)floor(s);
    #pragma unroll
    for(int k=0;k<4;k++){
        int kk = f + k - 1;
        idx[k] = min(max(kk, 0), oldn-1);
        wt[k]  = (float)cubicw(s - (double)kk);
    }
}

__constant__ int c_SH[3]={16,8,24};
__constant__ int c_SW[3]={9,4,13};
__constant__ int c_RB[3]={0,16,24};

// ---------------- k_prep (also zeroes g_stats) ----------------
__global__ void __launch_bounds__(256) k_prep(const float* __restrict__ w1,
                                              const float* __restrict__ spw,
                                              const float* __restrict__ w2){
    int tid=blockIdx.x*256+threadIdx.x;
    if(blockIdx.x==0){
        for(int i=threadIdx.x;i<Bb*144;i+=256) g_stats[i]=0.f;
    }
    for(int i=tid;i<240*96;i+=256*32){
        int n=i/96, k=i%96;
        float w = (n<192)? w1[n*96+k] : spw[(n-192)*96+k];
        unsigned hi,lo; tfsplit(w,hi,lo);
        g_w1hi[i]=__uint_as_float(hi);
        g_w1lo[i]=__uint_as_float(lo);
    }
    for(int i=tid;i<96*192;i+=256*32){
        float w = w2[i];
        unsigned hi,lo; tfsplit(w,hi,lo);
        g_w2hi[i]=__uint_as_float(hi);
        g_w2lo[i]=__uint_as_float(lo);
    }
}

// ---------------- k_filt1 ----------------
__global__ void __launch_bounds__(256) k_filt1(const float* __restrict__ cw0,
                                               const float* __restrict__ cw1,
                                               const float* __restrict__ cw2){
    __shared__ int   widx[65][4];
    __shared__ float wwt [65][4];
    __shared__ float2 rowb[13*Mm];
    int r = blockIdx.x;
    int s = (r<16)?0:((r<24)?1:2);
    int ih = r - c_RB[s];
    int ow = c_SW[s];
    const float* cws = (s==0)?cw0:((s==1)?cw1:cw2);
    int tid=threadIdx.x;
    if(tid<65) taps4(tid, ow, 65, widx[tid], wwt[tid]);
    const float2* src = (const float2*)(cws) + (size_t)ih*ow*Mm;
    for(int i=tid;i<ow*Mm;i+=256) rowb[i]=src[i];
    __syncthreads();
    float2* dst = g_tmp + (size_t)r*65*Mm;
    for(int e=tid;e<65*Mm;e+=256){
        int w=e/Mm, m=e%Mm;
        float ax=0.f, ay=0.f;
        #pragma unroll
        for(int a=0;a<4;a++){
            float wg=wwt[w][a];
            float2 v=rowb[widx[w][a]*Mm+m];
            ax+=wg*v.x; ay+=wg*v.y;
        }
        dst[e]=make_float2(ax,ay);
    }
}

// ---------------- k_filt2 ----------------
__global__ void __launch_bounds__(128) k_filt2(){
    __shared__ int   hidx[4];
    __shared__ float hwt [4];
    __shared__ float2 tile[48*65];
    int bid=blockIdx.x;
    int s  = bid/512;
    int rem= bid%512;
    int hq = rem/4;
    int m0 = (rem%4)*48;
    int tid=threadIdx.x;
    if(tid==0){
        int id[4]; float wt[4];
        taps4(hq, c_SH[s], 128, id, wt);
        #pragma unroll
        for(int a=0;a<4;a++){ hidx[a]=id[a]; hwt[a]=wt[a]; }
    }
    __syncthreads();
    const float2* base = g_tmp + (size_t)c_RB[s]*65*Mm;
    for(int e=tid;e<65*48;e+=128){
        int w=e/48, mm=e%48;
        int m=m0+mm;
        float ax=0.f, ay=0.f;
        #pragma unroll
        for(int a=0;a<4;a++){
            float2 v=base[(size_t)hidx[a]*65*Mm + w*Mm + m];
            ax+=hwt[a]*v.x; ay+=hwt[a]*v.y;
        }
        tile[mm*65+w]=make_float2(ax,ay);
    }
    __syncthreads();
    int hb=br7(hq);
    for(int e=tid;e<48*65;e+=128){
        int mm=e/65, w=e%65;
        g_filt[(size_t)(s*Mm+m0+mm)*SPEC + hb*65 + w]=tile[mm*65+w];
    }
}

// ---------------- k_pw1: tf32 MMA pwconv1+Soa + routing stats ----------------
// n-grouped MMA: load B frags for 6 n's, then 3 passes of 6 independent MMAs
#define P1_XS  0
#define P1_WH  (P1_XS+12800)
#define P1_WL  (P1_WH+12480)
#define P1_SB  (P1_WL+12480)
#define P1_BNP (P1_SB+6336)
#define P1_RED (P1_BNP+96)
#define P1_TOT (P1_RED+192)
__global__ void __launch_bounds__(256) k_pw1(const float* __restrict__ x,
                                             const float* __restrict__ s1,
                                             const float* __restrict__ b1,
                                             const float* __restrict__ bng,
                                             const float* __restrict__ bnb,
                                             const float* __restrict__ bnm,
                                             const float* __restrict__ bnv){
    float* S=(float*)SMEM;
    float* xs  = S+P1_XS;      // [128][100]
    float* wsh = S+P1_WH;      // [240][52]
    float* wsl = S+P1_WL;
    float* sb  = S+P1_SB;      // [48][132]
    float* bnp = S+P1_BNP;
    float* red = S+P1_RED;
    int tid=threadIdx.x;
    int b=blockIdx.y, pix0=blockIdx.x*128;
    const float* xb = x + ((size_t)b*16384 + pix0)*96;
    for(int i=tid;i<128*96;i+=256){ int p=i/96,c=i%96; xs[p*100+c]=xb[i]; }
    if(tid<48){
        float sc=rsqrtf(bnv[tid]+1e-5f)*bng[tid];
        bnp[tid]=sc;
        bnp[48+tid]=bnb[tid]-bnm[tid]*sc;
    }
    int warp=tid>>5, lane=tid&31;
    int gid=lane>>2, tig=lane&3;
    int pr0=warp*16;
    float C[30][4];
    #pragma unroll
    for(int n=0;n<30;n++){ C[n][0]=0.f;C[n][1]=0.f;C[n][2]=0.f;C[n][3]=0.f; }
    #pragma unroll 1
    for(int kh=0;kh<2;kh++){
        __syncthreads();
        for(int i=tid;i<240*48;i+=256){
            int n=i/48, kk=i%48;
            wsh[n*52+kk]=g_w1hi[n*96 + kh*48 + kk];
            wsl[n*52+kk]=g_w1lo[n*96 + kh*48 + kk];
        }
        __syncthreads();
        unsigned ah[6][4], al[6][4];
        #pragma unroll
        for(int kt=0;kt<6;kt++){
            int k0=kh*48+kt*8;
            float r0=xs[(pr0+gid  )*100 + k0+tig];
            float r1=xs[(pr0+gid+8)*100 + k0+tig];
            float r2=xs[(pr0+gid  )*100 + k0+tig+4];
            float r3=xs[(pr0+gid+8)*100 + k0+tig+4];
            tfsplit(r0,ah[kt][0],al[kt][0]);
            tfsplit(r1,ah[kt][1],al[kt][1]);
            tfsplit(r2,ah[kt][2],al[kt][2]);
            tfsplit(r3,ah[kt][3],al[kt][3]);
        }
        #pragma unroll
        for(int kt=0;kt<6;kt++){
            int kk=kt*8;
            #pragma unroll
            for(int ng=0;ng<5;ng++){
                unsigned bh0[6],bh1[6],bl0[6],bl1[6];
                #pragma unroll
                for(int u=0;u<6;u++){
                    int nrow=((ng*6+u)*8+gid)*52 + kk;
                    bh0[u]=__float_as_uint(wsh[nrow+tig]);
                    bh1[u]=__float_as_uint(wsh[nrow+tig+4]);
                    bl0[u]=__float_as_uint(wsl[nrow+tig]);
                    bl1[u]=__float_as_uint(wsl[nrow+tig+4]);
                }
                #pragma unroll
                for(int u=0;u<6;u++) mma8(C[ng*6+u], ah[kt], bh0[u], bh1[u]);
                #pragma unroll
                for(int u=0;u<6;u++) mma8(C[ng*6+u], al[kt], bh0[u], bh1[u]);
                #pragma unroll
                for(int u=0;u<6;u++) mma8(C[ng*6+u], ah[kt], bl0[u], bl1[u]);
            }
        }
    }
    // gctx sums from xs BEFORE region reuse
    float gsum=0.f;
    if(tid<96){
        #pragma unroll 4
        for(int p=0;p<128;p++) gsum+=xs[p*100+tid];
    }
    // sctx rows -> sb
    #pragma unroll
    for(int n=24;n<30;n++){
        int sc=(n-24)*8+2*tig;
        int p=pr0+gid;
        sb[sc*132+p]      =C[n][0];
        sb[(sc+1)*132+p]  =C[n][1];
        sb[sc*132+p+8]    =C[n][2];
        sb[(sc+1)*132+p+8]=C[n][3];
    }
    float scb=*s1, bib=*b1;
    __syncthreads();
    // stage m<192 outputs (Soa applied) into outs[192][132]
    float* outs = S;   // 192*132 = 25344 floats < 37760
    #pragma unroll
    for(int n=0;n<24;n++){
        int mch=n*8+2*tig;
        int p=pr0+gid;
        float v0=fmaxf(C[n][0],0.f), v1=fmaxf(C[n][1],0.f);
        float v2=fmaxf(C[n][2],0.f), v3=fmaxf(C[n][3],0.f);
        outs[mch*132+p]      =scb*v0*v0+bib;
        outs[(mch+1)*132+p]  =scb*v1*v1+bib;
        outs[mch*132+p+8]    =scb*v2*v2+bib;
        outs[(mch+1)*132+p+8]=scb*v3*v3+bib;
    }
    if(tid<96) atomicAdd(&g_stats[b*144+tid], gsum);
    __syncthreads();
    // coalesced write to g_xpre
    float* op = g_xpre + (size_t)b*Mm*16384 + pix0;
    for(int i=tid;i<192*128;i+=256){
        int mm=i>>7, p=i&127;
        op[(size_t)mm*16384+p]=outs[mm*132+p];
    }
    // sctx reduce
    if(tid<192){
        int sc=tid>>2, q=tid&3;
        float scale=bnp[sc], shift=bnp[48+sc];
        float s=0.f;
        #pragma unroll 4
        for(int p=q*32;p<q*32+32;p++) s+=fmaxf(sb[sc*132+p]*scale+shift,0.f);
        red[sc*4+q]=s;
    }
    __syncthreads();
    if(tid<48) atomicAdd(&g_stats[b*144+96+tid], red[4*tid]+red[4*tid+1]+red[4*tid+2]+red[4*tid+3]);
}

// ---------------- k_mlp ----------------
#define MLP_SF   0
#define MLP_FC1  (8*145)
#define MLP_HM   (MLP_FC1+36*145)
#define MLP_FC2  (MLP_HM+8*37)
#define MLP_TOT  (MLP_FC2+576*37)
__global__ void __launch_bounds__(512) k_mlp(const float* __restrict__ fc1,
                                             const float* __restrict__ fc2,
                                             const float* __restrict__ msc,
                                             const float* __restrict__ mbi){
    float* S=(float*)SMEM;
    float* sf  = S+MLP_SF;
    float* f1s = S+MLP_FC1;
    float* hm  = S+MLP_HM;
    float* f2s = S+MLP_FC2;
    int tid=threadIdx.x;
    for(int i=tid;i<8*144;i+=512){ int b=i/144,k=i%144; sf[b*145+k]=g_stats[i]*(1.f/16384.f); }
    for(int i=tid;i<36*144;i+=512){ int j=i/144,k=i%144; f1s[j*145+k]=fc1[i]; }
    for(int i=tid;i<576*36;i+=512){ int j=i/36,k=i%36; f2s[j*37+k]=fc2[i]; }
    __syncthreads();
    if(tid<288){
        int b=tid/36, j=tid%36;
        float a=0.f;
        #pragma unroll 8
        for(int k=0;k<144;k++) a+=sf[b*145+k]*f1s[j*145+k];
        float r=fmaxf(a,0.f);
        hm[b*37+j]=(*msc)*r*r + (*mbi);
    }
    __syncthreads();
    for(int idx=tid; idx<8*Mm; idx+=512){
        int b=idx/Mm, m=idx%Mm;
        float lg[3];
        #pragma unroll
        for(int s=0;s<3;s++){
            float a=0.f;
            const float* f2=f2s+(size_t)(s*Mm+m)*37;
            #pragma unroll
            for(int k=0;k<36;k++) a+=hm[b*37+k]*f2[k];
            lg[s]=a;
        }
        float mx=fmaxf(lg[0],fmaxf(lg[1],lg[2]));
        float e0=expf(lg[0]-mx), e1=expf(lg[1]-mx), e2=expf(lg[2]-mx);
        float inv=1.f/(e0+e1+e2);
        g_r[(b*3+0)*Mm+m]=e0*inv;
        g_r[(b*3+1)*Mm+m]=e1*inv;
        g_r[(b*3+2)*Mm+m]=e2*inv;
    }
}

// ---------------- k_fft (512 thr) ----------------
__global__ void __launch_bounds__(512) k_fft(){
    float2* sh=(float2*)SMEM;
    float2* sm = sh;
    float2* tmpAll = sh + SPEC;
    float2* tw = sh + SPEC + 2048;
    int tid=threadIdx.x, lane=tid&31, wid=tid>>5;
    int bm=blockIdx.x;
    int b=bm/Mm, m=bm%Mm;
    float* plane = g_xpre + (size_t)bm*16384;
    if(tid<64){
        float s,c;
        sincospif((float)tid*(1.0f/64.0f), &s, &c);
        tw[tid]=make_float2(c,-s);
    }
    __syncthreads();
    float2* tmp = tmpAll + wid*128;
    // Phase A: coalesced loads, bit-reversed LDS gather
    for(int pr=wid; pr<64; pr+=16){
        int ra=2*pr, rb=ra+1;
        #pragma unroll
        for(int t=0;t<4;t++){
            int idx=t*32+lane;
            tmp[idx]=make_float2(plane[ra*128+idx], plane[rb*128+idx]);
        }
        __syncwarp();
        float2 z[4];
        #pragma unroll
        for(int j=0;j<4;j++) z[j]=tmp[br7(j*32+lane)];
        fft128_dit<false>(z,tw,lane);
        __syncwarp();
        #pragma unroll
        for(int j=0;j<4;j++) tmp[j*32+lane]=z[j];
        __syncwarp();
        #pragma unroll
        for(int t=0;t<2;t++){
            int k=t*32+lane;
            float2 Zk=tmp[k], Zc=tmp[(128-k)&127];
            sm[ra*65+k]=make_float2(0.5f*(Zk.x+Zc.x), 0.5f*(Zk.y-Zc.y));
            sm[rb*65+k]=make_float2(0.5f*(Zk.y+Zc.y), 0.5f*(Zc.x-Zk.x));
        }
        if(lane==0){
            float2 Zk=tmp[64];
            sm[ra*65+64]=make_float2(Zk.x,0.f);
            sm[rb*65+64]=make_float2(Zk.y,0.f);
        }
        __syncwarp();
    }
    __syncthreads();
    for(int col=wid; col<65; col+=16){
        float2 z[4];
        #pragma unroll
        for(int j=0;j<4;j++) z[j]=sm[(j*32+lane)*65+col];
        fft128_dif(z,tw,lane);
        #pragma unroll
        for(int j=0;j<4;j++) sm[(j*32+lane)*65+col]=z[j];
    }
    __syncthreads();
    {
        float r0=g_r[(b*3+0)*Mm+m], r1=g_r[(b*3+1)*Mm+m], r2=g_r[(b*3+2)*Mm+m];
        const float2* f0=g_filt + (size_t)(0*Mm+m)*SPEC;
        const float2* f1=g_filt + (size_t)(1*Mm+m)*SPEC;
        const float2* f2=g_filt + (size_t)(2*Mm+m)*SPEC;
        for(int e=tid;e<SPEC;e+=512){
            float2 a=f0[e], bb=f1[e], c=f2[e];
            float2 comb=make_float2(a.x*r0+bb.x*r1+c.x*r2, a.y*r0+bb.y*r1+c.y*r2);
            sm[e]=cmulf(sm[e],comb);
        }
    }
    __syncthreads();
    for(int col=wid; col<65; col+=16){
        float2 z[4];
        #pragma unroll
        for(int j=0;j<4;j++) z[j]=sm[(j*32+lane)*65+col];
        fft128_dit<true>(z,tw,lane);
        #pragma unroll
        for(int j=0;j<4;j++) sm[(j*32+lane)*65+col]=z[j];
    }
    __syncthreads();
    for(int pr=wid; pr<64; pr+=16){
        int ra=2*pr, rb=ra+1;
        float2 z[4];
        #pragma unroll
        for(int j=0;j<4;j++){
            int p=j*32+lane, k=br7(p);
            float2 zz;
            if(k<=64){
                float2 a=sm[ra*65+k], bb=sm[rb*65+k];
                if(k==0||k==64){ a.y=0.f; bb.y=0.f; }
                zz=make_float2(a.x-bb.y, a.y+bb.x);
            } else {
                int kk=128-k;
                float2 a=sm[ra*65+kk], bb=sm[rb*65+kk];
                zz=make_float2(a.x+bb.y, bb.x-a.y);
            }
            z[j]=zz;
        }
        fft128_dit<true>(z,tw,lane);
        #pragma unroll
        for(int j=0;j<4;j++){
            int p=j*32+lane;
            plane[ra*128+p]=z[j].x*INV_HW;
            plane[rb*128+p]=z[j].y*INV_HW;
        }
    }
}

// ---------------- k_pw2: tf32 MMA pwconv2 (n-grouped) ----------------
#define P2_AS  0
#define P2_WH  (P2_AS+25088)
#define P2_WL  (P2_WH+9600)
#define P2_TOT (P2_WL+9600)
__global__ void __launch_bounds__(256) k_pw2(float* __restrict__ out){
    float* S=(float*)SMEM;
    float* As = S+P2_AS;      // [128][196] k-major
    float* wh = S+P2_WH;
    float* wl = S+P2_WL;
    int tid=threadIdx.x;
    int b=blockIdx.y, pix0=blockIdx.x*128;
    const float* ap = g_xpre + (size_t)b*Mm*16384 + pix0;
    for(int i=tid;i<192*128;i+=256){
        int mm=i>>7, p=i&127;
        As[p*196+mm]=ap[(size_t)mm*16384+p];
    }
    int warp=tid>>5, lane=tid&31;
    int gid=lane>>2, tig=lane&3;
    int pr0=warp*16;
    float C[12][4];
    #pragma unroll
    for(int n=0;n<12;n++){ C[n][0]=0.f;C[n][1]=0.f;C[n][2]=0.f;C[n][3]=0.f; }
    #pragma unroll 1
    for(int kh=0;kh<2;kh++){
        __syncthreads();
        for(int i=tid;i<96*96;i+=256){
            int c=i/96, kk=i%96;
            wh[c*100+kk]=g_w2hi[c*192 + kh*96 + kk];
            wl[c*100+kk]=g_w2lo[c*192 + kh*96 + kk];
        }
        __syncthreads();
        unsigned ah[12][4], al[12][4];
        #pragma unroll
        for(int kt=0;kt<12;kt++){
            int k0=kh*96+kt*8;
            float r0=As[(pr0+gid  )*196 + k0+tig];
            float r1=As[(pr0+gid+8)*196 + k0+tig];
            float r2=As[(pr0+gid  )*196 + k0+tig+4];
            float r3=As[(pr0+gid+8)*196 + k0+tig+4];
            tfsplit(r0,ah[kt][0],al[kt][0]);
            tfsplit(r1,ah[kt][1],al[kt][1]);
            tfsplit(r2,ah[kt][2],al[kt][2]);
            tfsplit(r3,ah[kt][3],al[kt][3]);
        }
        #pragma unroll
        for(int kt=0;kt<12;kt++){
            int kk=kt*8;
            #pragma unroll
            for(int ng=0;ng<2;ng++){
                unsigned bh0[6],bh1[6],bl0[6],bl1[6];
                #pragma unroll
                for(int u=0;u<6;u++){
                    int nrow=((ng*6+u)*8+gid)*100 + kk;
                    bh0[u]=__float_as_uint(wh[nrow+tig]);
                    bh1[u]=__float_as_uint(wh[nrow+tig+4]);
                    bl0[u]=__float_as_uint(wl[nrow+tig]);
                    bl1[u]=__float_as_uint(wl[nrow+tig+4]);
                }
                #pragma unroll
                for(int u=0;u<6;u++) mma8(C[ng*6+u], ah[kt], bh0[u], bh1[u]);
                #pragma unroll
                for(int u=0;u<6;u++) mma8(C[ng*6+u], al[kt], bh0[u], bh1[u]);
                #pragma unroll
                for(int u=0;u<6;u++) mma8(C[ng*6+u], ah[kt], bl0[u], bl1[u]);
            }
        }
    }
    __syncthreads();
    // stage into outs[128][100] then coalesced write
    float* outs=S;
    #pragma unroll
    for(int n=0;n<12;n++){
        int c0=n*8+2*tig;
        int p=pr0+gid;
        outs[p*100+c0]      =C[n][0];
        outs[p*100+c0+1]    =C[n][1];
        outs[(p+8)*100+c0]  =C[n][2];
        outs[(p+8)*100+c0+1]=C[n][3];
    }
    __syncthreads();
    float* op = out + ((size_t)b*16384 + pix0)*96;
    for(int i=tid;i<128*96;i+=256){
        int p=i/96, c=i%96;
        op[i]=outs[p*100+c];
    }
}

// ---------------- launch ----------------
extern "C" void kernel_launch(void* const* d_in, const int* in_sizes, int n_in,
                              void* d_out, int out_size){
    (void)in_sizes; (void)n_in; (void)out_size;
    const float* x   =(const float*)d_in[0];
    const float* w1  =(const float*)d_in[1];
    const float* s1  =(const float*)d_in[2];
    const float* b1  =(const float*)d_in[3];
    const float* cw0 =(const float*)d_in[4];
    const float* cw1 =(const float*)d_in[5];
    const float* cw2 =(const float*)d_in[6];
    const float* spw =(const float*)d_in[7];
    const float* bng =(const float*)d_in[8];
    const float* bnb =(const float*)d_in[9];
    const float* bnm =(const float*)d_in[10];
    const float* bnv =(const float*)d_in[11];
    const float* fc1 =(const float*)d_in[12];
    const float* msc =(const float*)d_in[13];
    const float* mbi =(const float*)d_in[14];
    const float* fc2 =(const float*)d_in[15];
    const float* w2  =(const float*)d_in[16];
    float* out=(float*)d_out;

    const int SM_PW1 = P1_TOT*4;
    const int SM_FFT = (SPEC+2048+64)*8;
    const int SM_PW2 = P2_TOT*4;
    const int SM_MLP = MLP_TOT*4;

    cudaFuncSetAttribute(k_pw1, cudaFuncAttributeMaxDynamicSharedMemorySize, SM_PW1);
    cudaFuncSetAttribute(k_fft, cudaFuncAttributeMaxDynamicSharedMemorySize, SM_FFT);
    cudaFuncSetAttribute(k_pw2, cudaFuncAttributeMaxDynamicSharedMemorySize, SM_PW2);
    cudaFuncSetAttribute(k_mlp, cudaFuncAttributeMaxDynamicSharedMemorySize, SM_MLP);

    k_prep<<<32, 256>>>(w1, spw, w2);
    k_filt1<<<48, 256>>>(cw0, cw1, cw2);
    k_filt2<<<3*128*4, 128>>>();
    k_pw1<<<dim3(128,Bb), 256, SM_PW1>>>(x, s1, b1, bng, bnb, bnm, bnv);
    k_mlp<<<1, 512, SM_MLP>>>(fc1, fc2, msc, mbi);
    k_fft<<<Bb*Mm, 512, SM_FFT>>>();
    k_pw2<<<dim3(128,Bb), 256, SM_PW2>>>(out);
}

// round 13
// speedup vs baseline: 1.0848x; 1.0824x over previous
#include <cuda_runtime.h>
#include <math.h>

#define DINLINE __device__ __forceinline__

// ---------------- problem constants ----------------
#define Bb 8
#define Hh 128
#define Ww 128
#define Cc 96
#define Mm 192
#define SPEC (128*65)
#define INV_HW (1.0f/16384.0f)

// ---------------- device scratch ----------------
__device__ float  g_xpre[(size_t)Bb*Mm*Hh*Ww];     // reused in-place for xsp
__device__ float2 g_filt[(size_t)3*Mm*SPEC];       // resized filters (BR h order)
__device__ float2 g_tmp[(size_t)48*65*Mm];         // separable-resize intermediate
__device__ float  g_r[Bb*3*Mm];
__device__ float  g_stats[Bb*144];
// tf32-split weights: rows 0..191 = w1, rows 192..239 = spw
__device__ float  g_w1hi[240*96], g_w1lo[240*96];

extern __shared__ __align__(16) char SMEM[];

// ---------------- helpers ----------------
DINLINE int br7(int p){ return (int)(__brev((unsigned)p)>>25); }
DINLINE float2 cmulf(float2 a, float2 b){ return make_float2(a.x*b.x - a.y*b.y, a.x*b.y + a.y*b.x); }
DINLINE float2 f2add(float2 a,float2 b){ return make_float2(a.x+b.x, a.y+b.y); }
DINLINE float2 f2sub(float2 a,float2 b){ return make_float2(a.x-b.x, a.y-b.y); }
DINLINE float2 shflx(float2 v,int m){
    v.x = __shfl_xor_sync(0xffffffffu, v.x, m);
    v.y = __shfl_xor_sync(0xffffffffu, v.y, m);
    return v;
}
// tf32 helpers
DINLINE unsigned f2tf(float x){ unsigned r; asm("cvt.rna.tf32.f32 %0,%1;":"=r"(r):"f"(x)); return r; }
DINLINE void tfsplit(float x, unsigned& hi, unsigned& lo){
    hi = f2tf(x);
    lo = f2tf(x - __uint_as_float(hi));
}
DINLINE void mma8(float c[4], const unsigned a[4], unsigned b0, unsigned b1){
    asm("mma.sync.aligned.m16n8k8.row.col.f32.tf32.tf32.f32 "
        "{%0,%1,%2,%3},{%4,%5,%6,%7},{%8,%9},{%0,%1,%2,%3};"
        : "+f"(c[0]),"+f"(c[1]),"+f"(c[2]),"+f"(c[3])
        : "r"(a[0]),"r"(a[1]),"r"(a[2]),"r"(a[3]),"r"(b0),"r"(b1));
}
// packed f32x2 FMA (Blackwell)
DINLINE unsigned long long dup2(float x){
    unsigned long long r;
    asm("mov.b64 %0,{%1,%1};":"=l"(r):"f"(x));
    return r;
}
DINLINE void ffma2(unsigned long long& d, unsigned long long a, unsigned long long b){
    asm("fma.rn.f32x2 %0,%1,%2,%3;":"=l"(d):"l"(a),"l"(b),"l"(d));
}
DINLINE void unpk2(unsigned long long v, float& lo, float& hi){
    asm("mov.b64 {%0,%1},%2;":"=f"(lo),"=f"(hi):"l"(v));
}

// Forward DIF 128-pt FFT
DINLINE void fft128_dif(float2 z[4], const float2* tw, int lane){
    #pragma unroll
    for(int j=0;j<2;j++){
        int k=j*32+lane;
        float2 u=z[j], v=z[j+2];
        z[j]=f2add(u,v);
        z[j+2]=cmulf(f2sub(u,v), tw[k]);
    }
    {
        float2 w=tw[2*lane];
        float2 u=z[0],v=z[1];
        z[0]=f2add(u,v); z[1]=cmulf(f2sub(u,v),w);
        u=z[2]; v=z[3];
        z[2]=f2add(u,v); z[3]=cmulf(f2sub(u,v),w);
    }
    #pragma unroll
    for(int d=16; d>=1; d>>=1){
        int k=lane&(d-1);
        float2 w=tw[k*(64/d)];
        bool up=(lane&d)!=0;
        #pragma unroll
        for(int j=0;j<4;j++){
            float2 o=shflx(z[j],d);
            float2 r;
            if(up) r=cmulf(make_float2(o.x - z[j].x, o.y - z[j].y), w);
            else   r=make_float2(z[j].x+o.x, z[j].y+o.y);
            z[j]=r;
        }
    }
}

// DIT 128-pt FFT
template<bool CONJ>
DINLINE void fft128_dit(float2 z[4], const float2* tw, int lane){
    #pragma unroll
    for(int d=1; d<=16; d<<=1){
        int k=lane&(d-1);
        float2 w=tw[k*(64/d)];
        if(CONJ) w.y=-w.y;
        bool up=(lane&d)!=0;
        #pragma unroll
        for(int j=0;j<4;j++){
            float2 o=shflx(z[j],d);
            float2 r;
            if(up){
                float2 t=cmulf(w, z[j]);
                r=make_float2(o.x-t.x, o.y-t.y);
            } else {
                float2 t=cmulf(w, o);
                r=make_float2(z[j].x+t.x, z[j].y+t.y);
            }
            z[j]=r;
        }
    }
    {
        float2 w=tw[2*lane]; if(CONJ) w.y=-w.y;
        float2 t=cmulf(w,z[1]); float2 u=z[0];
        z[0]=f2add(u,t); z[1]=f2sub(u,t);
        t=cmulf(w,z[3]); u=z[2];
        z[2]=f2add(u,t); z[3]=f2sub(u,t);
    }
    #pragma unroll
    for(int j=0;j<2;j++){
        int k=j*32+lane;
        float2 w=tw[k]; if(CONJ) w.y=-w.y;
        float2 t=cmulf(w,z[j+2]); float2 u=z[j];
        z[j]=f2add(u,t);
        z[j+2]=f2sub(u,t);
    }
}

// ---------------- bicubic resize taps ----------------
DINLINE double cubicw(double t){
    t = fabs(t);
    const double a = -0.75;
    if(t <= 1.0) return ((a+2.0)*t - (a+3.0))*t*t + 1.0;
    if(t <  2.0) return a*(((t-5.0)*t+8.0)*t-4.0);
    return 0.0;
}
DINLINE void taps4(int j, int oldn, int newn, int* idx, float* wt){
    double s = (newn > 1) ? (double)j * (double)(oldn-1) / (double)(newn-1) : 0.0;
    int f = (int)floor(s);
    #pragma unroll
    for(int k=0;k<4;k++){
        int kk = f + k - 1;
        idx[k] = min(max(kk, 0), oldn-1);
        wt[k]  = (float)cubicw(s - (double)kk);
    }
}

__constant__ int c_SH[3]={16,8,24};
__constant__ int c_SW[3]={9,4,13};
__constant__ int c_RB[3]={0,16,24};

// ---------------- k_prep: zero stats + tf32 split of w1/spw ----------------
__global__ void __launch_bounds__(256) k_prep(const float* __restrict__ w1,
                                              const float* __restrict__ spw){
    int tid=blockIdx.x*256+threadIdx.x;
    if(blockIdx.x==0){
        for(int i=threadIdx.x;i<Bb*144;i+=256) g_stats[i]=0.f;
    }
    for(int i=tid;i<240*96;i+=256*16){
        int n=i/96, k=i%96;
        float w = (n<192)? w1[n*96+k] : spw[(n-192)*96+k];
        unsigned hi,lo; tfsplit(w,hi,lo);
        g_w1hi[i]=__uint_as_float(hi);
        g_w1lo[i]=__uint_as_float(lo);
    }
}

// ---------------- k_filt1 ----------------
__global__ void __launch_bounds__(256) k_filt1(const float* __restrict__ cw0,
                                               const float* __restrict__ cw1,
                                               const float* __restrict__ cw2){
    __shared__ int   widx[65][4];
    __shared__ float wwt [65][4];
    __shared__ float2 rowb[13*Mm];
    int r = blockIdx.x;
    int s = (r<16)?0:((r<24)?1:2);
    int ih = r - c_RB[s];
    int ow = c_SW[s];
    const float* cws = (s==0)?cw0:((s==1)?cw1:cw2);
    int tid=threadIdx.x;
    if(tid<65) taps4(tid, ow, 65, widx[tid], wwt[tid]);
    const float2* src = (const float2*)(cws) + (size_t)ih*ow*Mm;
    for(int i=tid;i<ow*Mm;i+=256) rowb[i]=src[i];
    __syncthreads();
    float2* dst = g_tmp + (size_t)r*65*Mm;
    for(int e=tid;e<65*Mm;e+=256){
        int w=e/Mm, m=e%Mm;
        float ax=0.f, ay=0.f;
        #pragma unroll
        for(int a=0;a<4;a++){
            float wg=wwt[w][a];
            float2 v=rowb[widx[w][a]*Mm+m];
            ax+=wg*v.x; ay+=wg*v.y;
        }
        dst[e]=make_float2(ax,ay);
    }
}

// ---------------- k_filt2 ----------------
__global__ void __launch_bounds__(128) k_filt2(){
    __shared__ int   hidx[4];
    __shared__ float hwt [4];
    __shared__ float2 tile[48*65];
    int bid=blockIdx.x;
    int s  = bid/512;
    int rem= bid%512;
    int hq = rem/4;
    int m0 = (rem%4)*48;
    int tid=threadIdx.x;
    if(tid==0){
        int id[4]; float wt[4];
        taps4(hq, c_SH[s], 128, id, wt);
        #pragma unroll
        for(int a=0;a<4;a++){ hidx[a]=id[a]; hwt[a]=wt[a]; }
    }
    __syncthreads();
    const float2* base = g_tmp + (size_t)c_RB[s]*65*Mm;
    for(int e=tid;e<65*48;e+=128){
        int w=e/48, mm=e%48;
        int m=m0+mm;
        float ax=0.f, ay=0.f;
        #pragma unroll
        for(int a=0;a<4;a++){
            float2 v=base[(size_t)hidx[a]*65*Mm + w*Mm + m];
            ax+=hwt[a]*v.x; ay+=hwt[a]*v.y;
        }
        tile[mm*65+w]=make_float2(ax,ay);
    }
    __syncthreads();
    int hb=br7(hq);
    for(int e=tid;e<48*65;e+=128){
        int mm=e/65, w=e%65;
        g_filt[(size_t)(s*Mm+m0+mm)*SPEC + hb*65 + w]=tile[mm*65+w];
    }
}

// ---------------- k_pw1: tf32 MMA pwconv1+Soa + routing stats (R12 version) ----------------
#define P1_XS  0
#define P1_WH  (P1_XS+12800)
#define P1_WL  (P1_WH+12480)
#define P1_SB  (P1_WL+12480)
#define P1_BNP (P1_SB+6336)
#define P1_RED (P1_BNP+96)
#define P1_TOT (P1_RED+192)
__global__ void __launch_bounds__(256) k_pw1(const float* __restrict__ x,
                                             const float* __restrict__ s1,
                                             const float* __restrict__ b1,
                                             const float* __restrict__ bng,
                                             const float* __restrict__ bnb,
                                             const float* __restrict__ bnm,
                                             const float* __restrict__ bnv){
    float* S=(float*)SMEM;
    float* xs  = S+P1_XS;      // [128][100]
    float* wsh = S+P1_WH;      // [240][52]
    float* wsl = S+P1_WL;
    float* sb  = S+P1_SB;      // [48][132]
    float* bnp = S+P1_BNP;
    float* red = S+P1_RED;
    int tid=threadIdx.x;
    int b=blockIdx.y, pix0=blockIdx.x*128;
    const float* xb = x + ((size_t)b*16384 + pix0)*96;
    for(int i=tid;i<128*96;i+=256){ int p=i/96,c=i%96; xs[p*100+c]=xb[i]; }
    if(tid<48){
        float sc=rsqrtf(bnv[tid]+1e-5f)*bng[tid];
        bnp[tid]=sc;
        bnp[48+tid]=bnb[tid]-bnm[tid]*sc;
    }
    int warp=tid>>5, lane=tid&31;
    int gid=lane>>2, tig=lane&3;
    int pr0=warp*16;
    float C[30][4];
    #pragma unroll
    for(int n=0;n<30;n++){ C[n][0]=0.f;C[n][1]=0.f;C[n][2]=0.f;C[n][3]=0.f; }
    #pragma unroll 1
    for(int kh=0;kh<2;kh++){
        __syncthreads();
        for(int i=tid;i<240*48;i+=256){
            int n=i/48, kk=i%48;
            wsh[n*52+kk]=g_w1hi[n*96 + kh*48 + kk];
            wsl[n*52+kk]=g_w1lo[n*96 + kh*48 + kk];
        }
        __syncthreads();
        unsigned ah[6][4], al[6][4];
        #pragma unroll
        for(int kt=0;kt<6;kt++){
            int k0=kh*48+kt*8;
            float r0=xs[(pr0+gid  )*100 + k0+tig];
            float r1=xs[(pr0+gid+8)*100 + k0+tig];
            float r2=xs[(pr0+gid  )*100 + k0+tig+4];
            float r3=xs[(pr0+gid+8)*100 + k0+tig+4];
            tfsplit(r0,ah[kt][0],al[kt][0]);
            tfsplit(r1,ah[kt][1],al[kt][1]);
            tfsplit(r2,ah[kt][2],al[kt][2]);
            tfsplit(r3,ah[kt][3],al[kt][3]);
        }
        #pragma unroll
        for(int kt=0;kt<6;kt++){
            int kk=kt*8;
            #pragma unroll
            for(int ng=0;ng<5;ng++){
                unsigned bh0[6],bh1[6],bl0[6],bl1[6];
                #pragma unroll
                for(int u=0;u<6;u++){
                    int nrow=((ng*6+u)*8+gid)*52 + kk;
                    bh0[u]=__float_as_uint(wsh[nrow+tig]);
                    bh1[u]=__float_as_uint(wsh[nrow+tig+4]);
                    bl0[u]=__float_as_uint(wsl[nrow+tig]);
                    bl1[u]=__float_as_uint(wsl[nrow+tig+4]);
                }
                #pragma unroll
                for(int u=0;u<6;u++) mma8(C[ng*6+u], ah[kt], bh0[u], bh1[u]);
                #pragma unroll
                for(int u=0;u<6;u++) mma8(C[ng*6+u], al[kt], bh0[u], bh1[u]);
                #pragma unroll
                for(int u=0;u<6;u++) mma8(C[ng*6+u], ah[kt], bl0[u], bl1[u]);
            }
        }
    }
    // gctx sums from xs BEFORE region reuse
    float gsum=0.f;
    if(tid<96){
        #pragma unroll 4
        for(int p=0;p<128;p++) gsum+=xs[p*100+tid];
    }
    // sctx rows -> sb
    #pragma unroll
    for(int n=24;n<30;n++){
        int sc=(n-24)*8+2*tig;
        int p=pr0+gid;
        sb[sc*132+p]      =C[n][0];
        sb[(sc+1)*132+p]  =C[n][1];
        sb[sc*132+p+8]    =C[n][2];
        sb[(sc+1)*132+p+8]=C[n][3];
    }
    float scb=*s1, bib=*b1;
    __syncthreads();
    // stage m<192 outputs (Soa applied) into outs[192][132]
    float* outs = S;
    #pragma unroll
    for(int n=0;n<24;n++){
        int mch=n*8+2*tig;
        int p=pr0+gid;
        float v0=fmaxf(C[n][0],0.f), v1=fmaxf(C[n][1],0.f);
        float v2=fmaxf(C[n][2],0.f), v3=fmaxf(C[n][3],0.f);
        outs[mch*132+p]      =scb*v0*v0+bib;
        outs[(mch+1)*132+p]  =scb*v1*v1+bib;
        outs[mch*132+p+8]    =scb*v2*v2+bib;
        outs[(mch+1)*132+p+8]=scb*v3*v3+bib;
    }
    if(tid<96) atomicAdd(&g_stats[b*144+tid], gsum);
    __syncthreads();
    float* op = g_xpre + (size_t)b*Mm*16384 + pix0;
    for(int i=tid;i<192*128;i+=256){
        int mm=i>>7, p=i&127;
        op[(size_t)mm*16384+p]=outs[mm*132+p];
    }
    if(tid<192){
        int sc=tid>>2, q=tid&3;
        float scale=bnp[sc], shift=bnp[48+sc];
        float s=0.f;
        #pragma unroll 4
        for(int p=q*32;p<q*32+32;p++) s+=fmaxf(sb[sc*132+p]*scale+shift,0.f);
        red[sc*4+q]=s;
    }
    __syncthreads();
    if(tid<48) atomicAdd(&g_stats[b*144+96+tid], red[4*tid]+red[4*tid+1]+red[4*tid+2]+red[4*tid+3]);
}

// ---------------- k_mlp ----------------
#define MLP_SF   0
#define MLP_FC1  (8*145)
#define MLP_HM   (MLP_FC1+36*145)
#define MLP_FC2  (MLP_HM+8*37)
#define MLP_TOT  (MLP_FC2+576*37)
__global__ void __launch_bounds__(512) k_mlp(const float* __restrict__ fc1,
                                             const float* __restrict__ fc2,
                                             const float* __restrict__ msc,
                                             const float* __restrict__ mbi){
    float* S=(float*)SMEM;
    float* sf  = S+MLP_SF;
    float* f1s = S+MLP_FC1;
    float* hm  = S+MLP_HM;
    float* f2s = S+MLP_FC2;
    int tid=threadIdx.x;
    for(int i=tid;i<8*144;i+=512){ int b=i/144,k=i%144; sf[b*145+k]=g_stats[i]*(1.f/16384.f); }
    for(int i=tid;i<36*144;i+=512){ int j=i/144,k=i%144; f1s[j*145+k]=fc1[i]; }
    for(int i=tid;i<576*36;i+=512){ int j=i/36,k=i%36; f2s[j*37+k]=fc2[i]; }
    __syncthreads();
    if(tid<288){
        int b=tid/36, j=tid%36;
        float a=0.f;
        #pragma unroll 8
        for(int k=0;k<144;k++) a+=sf[b*145+k]*f1s[j*145+k];
        float r=fmaxf(a,0.f);
        hm[b*37+j]=(*msc)*r*r + (*mbi);
    }
    __syncthreads();
    for(int idx=tid; idx<8*Mm; idx+=512){
        int b=idx/Mm, m=idx%Mm;
        float lg[3];
        #pragma unroll
        for(int s=0;s<3;s++){
            float a=0.f;
            const float* f2=f2s+(size_t)(s*Mm+m)*37;
            #pragma unroll
            for(int k=0;k<36;k++) a+=hm[b*37+k]*f2[k];
            lg[s]=a;
        }
        float mx=fmaxf(lg[0],fmaxf(lg[1],lg[2]));
        float e0=expf(lg[0]-mx), e1=expf(lg[1]-mx), e2=expf(lg[2]-mx);
        float inv=1.f/(e0+e1+e2);
        g_r[(b*3+0)*Mm+m]=e0*inv;
        g_r[(b*3+1)*Mm+m]=e1*inv;
        g_r[(b*3+2)*Mm+m]=e2*inv;
    }
}

// ---------------- k_fft (512 thr, original Phase A) ----------------
__global__ void __launch_bounds__(512) k_fft(){
    float2* sh=(float2*)SMEM;
    float2* sm = sh;
    float2* tmpAll = sh + SPEC;
    float2* tw = sh + SPEC + 2048;
    int tid=threadIdx.x, lane=tid&31, wid=tid>>5;
    int bm=blockIdx.x;
    int b=bm/Mm, m=bm%Mm;
    float* plane = g_xpre + (size_t)bm*16384;
    if(tid<64){
        float s,c;
        sincospif((float)tid*(1.0f/64.0f), &s, &c);
        tw[tid]=make_float2(c,-s);
    }
    __syncthreads();
    float2* tmp = tmpAll + wid*128;
    for(int pr=wid; pr<64; pr+=16){
        int ra=2*pr, rb=ra+1;
        float2 z[4];
        #pragma unroll
        for(int j=0;j<4;j++){
            int p=j*32+lane, q=br7(p);
            z[j]=make_float2(plane[ra*128+q], plane[rb*128+q]);
        }
        fft128_dit<false>(z,tw,lane);
        #pragma unroll
        for(int j=0;j<4;j++) tmp[j*32+lane]=z[j];
        __syncwarp();
        #pragma unroll
        for(int t=0;t<2;t++){
            int k=t*32+lane;
            float2 Zk=tmp[k], Zc=tmp[(128-k)&127];
            sm[ra*65+k]=make_float2(0.5f*(Zk.x+Zc.x), 0.5f*(Zk.y-Zc.y));
            sm[rb*65+k]=make_float2(0.5f*(Zk.y+Zc.y), 0.5f*(Zc.x-Zk.x));
        }
        if(lane==0){
            float2 Zk=tmp[64];
            sm[ra*65+64]=make_float2(Zk.x,0.f);
            sm[rb*65+64]=make_float2(Zk.y,0.f);
        }
        __syncwarp();
    }
    __syncthreads();
    for(int col=wid; col<65; col+=16){
        float2 z[4];
        #pragma unroll
        for(int j=0;j<4;j++) z[j]=sm[(j*32+lane)*65+col];
        fft128_dif(z,tw,lane);
        #pragma unroll
        for(int j=0;j<4;j++) sm[(j*32+lane)*65+col]=z[j];
    }
    __syncthreads();
    {
        float r0=g_r[(b*3+0)*Mm+m], r1=g_r[(b*3+1)*Mm+m], r2=g_r[(b*3+2)*Mm+m];
        const float2* f0=g_filt + (size_t)(0*Mm+m)*SPEC;
        const float2* f1=g_filt + (size_t)(1*Mm+m)*SPEC;
        const float2* f2=g_filt + (size_t)(2*Mm+m)*SPEC;
        for(int e=tid;e<SPEC;e+=512){
            float2 a=f0[e], bb=f1[e], c=f2[e];
            float2 comb=make_float2(a.x*r0+bb.x*r1+c.x*r2, a.y*r0+bb.y*r1+c.y*r2);
            sm[e]=cmulf(sm[e],comb);
        }
    }
    __syncthreads();
    for(int col=wid; col<65; col+=16){
        float2 z[4];
        #pragma unroll
        for(int j=0;j<4;j++) z[j]=sm[(j*32+lane)*65+col];
        fft128_dit<true>(z,tw,lane);
        #pragma unroll
        for(int j=0;j<4;j++) sm[(j*32+lane)*65+col]=z[j];
    }
    __syncthreads();
    for(int pr=wid; pr<64; pr+=16){
        int ra=2*pr, rb=ra+1;
        float2 z[4];
        #pragma unroll
        for(int j=0;j<4;j++){
            int p=j*32+lane, k=br7(p);
            float2 zz;
            if(k<=64){
                float2 a=sm[ra*65+k], bb=sm[rb*65+k];
                if(k==0||k==64){ a.y=0.f; bb.y=0.f; }
                zz=make_float2(a.x-bb.y, a.y+bb.x);
            } else {
                int kk=128-k;
                float2 a=sm[ra*65+kk], bb=sm[rb*65+kk];
                zz=make_float2(a.x+bb.y, bb.x-a.y);
            }
            z[j]=zz;
        }
        fft128_dit<true>(z,tw,lane);
        #pragma unroll
        for(int j=0;j<4;j++){
            int p=j*32+lane;
            plane[ra*128+p]=z[j].x*INV_HW;
            plane[rb*128+p]=z[j].y*INV_HW;
        }
    }
}

// ---------------- k_pw2 (512 thr, FFMA2, m-major weights — proven R7 version) ----------------
#define PW2_AS   0
#define PW2_W2   (PW2_AS+24768)
#define PW2_TOT  (PW2_W2+192*98)
__global__ void __launch_bounds__(512) k_pw2(const float* __restrict__ w2,
                                             float* __restrict__ out){
    float* S=(float*)SMEM;
    float* As  = S+PW2_AS;     // [m][129]
    float* w2m = S+PW2_W2;     // [m][98] c-contiguous
    int tid=threadIdx.x;
    int b=blockIdx.y, pix0=blockIdx.x*128;
    const float* ap = g_xpre + (size_t)b*Mm*16384 + pix0;
    for(int i=tid;i<192*128;i+=512){
        int mm=i>>7, p=i&127;
        As[mm*129+p]=ap[(size_t)mm*16384+p];
    }
    for(int i=tid;i<96*192;i+=512){
        int c=i/192, m=i%192;
        w2m[m*98+c]=w2[i];
    }
    __syncthreads();
    int tx=tid&15, ty=tid>>4;    // ty 0..31; c pairs 2tx+32j, j=0..2
    const unsigned long long* w2p=(const unsigned long long*)w2m;   // [m][49]
    unsigned long long acc[4][3];
    #pragma unroll
    for(int i=0;i<4;i++)
        #pragma unroll
        for(int j=0;j<3;j++) acc[i][j]=0ull;
    for(int m=0;m<192;m++){
        unsigned long long xd[4], wv[3];
        #pragma unroll
        for(int i=0;i<4;i++) xd[i]=dup2(As[m*129 + ty+32*i]);
        #pragma unroll
        for(int j=0;j<3;j++) wv[j]=w2p[m*49 + tx+16*j];
        #pragma unroll
        for(int i=0;i<4;i++)
            #pragma unroll
            for(int j=0;j<3;j++) ffma2(acc[i][j], xd[i], wv[j]);
    }
    __syncthreads();
    float* outs=S;            // 128*97
    #pragma unroll
    for(int i=0;i<4;i++){
        int p=ty+32*i;
        #pragma unroll
        for(int j=0;j<3;j++){
            int c0=2*tx+32*j;
            float lo,hi;
            unpk2(acc[i][j], lo, hi);
            outs[p*97+c0]=lo;
            outs[p*97+c0+1]=hi;
        }
    }
    __syncthreads();
    float* op = out + ((size_t)b*16384 + pix0)*96;
    for(int i=tid;i<128*96;i+=512){
        int p=i/96, c=i%96;
        op[i]=outs[p*97+c];
    }
}

// ---------------- launch ----------------
extern "C" void kernel_launch(void* const* d_in, const int* in_sizes, int n_in,
                              void* d_out, int out_size){
    (void)in_sizes; (void)n_in; (void)out_size;
    const float* x   =(const float*)d_in[0];
    const float* w1  =(const float*)d_in[1];
    const float* s1  =(const float*)d_in[2];
    const float* b1  =(const float*)d_in[3];
    const float* cw0 =(const float*)d_in[4];
    const float* cw1 =(const float*)d_in[5];
    const float* cw2 =(const float*)d_in[6];
    const float* spw =(const float*)d_in[7];
    const float* bng =(const float*)d_in[8];
    const float* bnb =(const float*)d_in[9];
    const float* bnm =(const float*)d_in[10];
    const float* bnv =(const float*)d_in[11];
    const float* fc1 =(const float*)d_in[12];
    const float* msc =(const float*)d_in[13];
    const float* mbi =(const float*)d_in[14];
    const float* fc2 =(const float*)d_in[15];
    const float* w2  =(const float*)d_in[16];
    float* out=(float*)d_out;

    const int SM_PW1 = P1_TOT*4;
    const int SM_FFT = (SPEC+2048+64)*8;
    const int SM_PW2 = PW2_TOT*4;
    const int SM_MLP = MLP_TOT*4;

    cudaFuncSetAttribute(k_pw1, cudaFuncAttributeMaxDynamicSharedMemorySize, SM_PW1);
    cudaFuncSetAttribute(k_fft, cudaFuncAttributeMaxDynamicSharedMemorySize, SM_FFT);
    cudaFuncSetAttribute(k_pw2, cudaFuncAttributeMaxDynamicSharedMemorySize, SM_PW2);
    cudaFuncSetAttribute(k_mlp, cudaFuncAttributeMaxDynamicSharedMemorySize, SM_MLP);

    k_prep<<<16, 256>>>(w1, spw);
    k_filt1<<<48, 256>>>(cw0, cw1, cw2);
    k_filt2<<<3*128*4, 128>>>();
    k_pw1<<<dim3(128,Bb), 256, SM_PW1>>>(x, s1, b1, bng, bnb, bnm, bnv);
    k_mlp<<<1, 512, SM_MLP>>>(fc1, fc2, msc, mbi);
    k_fft<<<Bb*Mm, 512, SM_FFT>>>();
    k_pw2<<<dim3(128,Bb), 512, SM_PW2>>>(w2, out);
}

// round 14
// speedup vs baseline: 1.1215x; 1.0338x over previous
#include <cuda_runtime.h>
#include <math.h>

#define DINLINE __device__ __forceinline__

// ---------------- problem constants ----------------
#define Bb 8
#define Hh 128
#define Ww 128
#define Cc 96
#define Mm 192
#define SPEC (128*65)
#define INV_HW (1.0f/16384.0f)

// ---------------- device scratch ----------------
__device__ float  g_xpre[(size_t)Bb*Mm*Hh*Ww];     // reused in-place for xsp
__device__ float2 g_filt[(size_t)3*Mm*SPEC];       // resized filters (BR h order)
__device__ float2 g_tmp[(size_t)48*65*Mm];         // separable-resize intermediate
__device__ float  g_r[Bb*3*Mm];
__device__ float  g_stats[Bb*144];
// paired tf32-split weights: [ncol][kh*24 + kt*4 + tig] = {v(k), v(k+4)}
// ncol 0..191 = w1 rows, 192..239 = spw rows; k = kh*48 + kt*8 + tig
__device__ float2 g_w1hp[240*48];
__device__ float2 g_w1lp[240*48];

extern __shared__ __align__(16) char SMEM[];

// ---------------- helpers ----------------
DINLINE int br7(int p){ return (int)(__brev((unsigned)p)>>25); }
DINLINE float2 cmulf(float2 a, float2 b){ return make_float2(a.x*b.x - a.y*b.y, a.x*b.y + a.y*b.x); }
DINLINE float2 f2add(float2 a,float2 b){ return make_float2(a.x+b.x, a.y+b.y); }
DINLINE float2 f2sub(float2 a,float2 b){ return make_float2(a.x-b.x, a.y-b.y); }
DINLINE float2 shflx(float2 v,int m){
    v.x = __shfl_xor_sync(0xffffffffu, v.x, m);
    v.y = __shfl_xor_sync(0xffffffffu, v.y, m);
    return v;
}
// tf32 helpers
DINLINE unsigned f2tf(float x){ unsigned r; asm("cvt.rna.tf32.f32 %0,%1;":"=r"(r):"f"(x)); return r; }
DINLINE void tfsplit(float x, unsigned& hi, unsigned& lo){
    hi = f2tf(x);
    lo = f2tf(x - __uint_as_float(hi));
}
DINLINE void mma8(float c[4], const unsigned a[4], unsigned b0, unsigned b1){
    asm("mma.sync.aligned.m16n8k8.row.col.f32.tf32.tf32.f32 "
        "{%0,%1,%2,%3},{%4,%5,%6,%7},{%8,%9},{%0,%1,%2,%3};"
        : "+f"(c[0]),"+f"(c[1]),"+f"(c[2]),"+f"(c[3])
        : "r"(a[0]),"r"(a[1]),"r"(a[2]),"r"(a[3]),"r"(b0),"r"(b1));
}
// packed f32x2 FMA (Blackwell)
DINLINE unsigned long long dup2(float x){
    unsigned long long r;
    asm("mov.b64 %0,{%1,%1};":"=l"(r):"f"(x));
    return r;
}
DINLINE void ffma2(unsigned long long& d, unsigned long long a, unsigned long long b){
    asm("fma.rn.f32x2 %0,%1,%2,%3;":"=l"(d):"l"(a),"l"(b),"l"(d));
}
DINLINE void unpk2(unsigned long long v, float& lo, float& hi){
    asm("mov.b64 {%0,%1},%2;":"=f"(lo),"=f"(hi):"l"(v));
}

// Forward DIF 128-pt FFT
DINLINE void fft128_dif(float2 z[4], const float2* tw, int lane){
    #pragma unroll
    for(int j=0;j<2;j++){
        int k=j*32+lane;
        float2 u=z[j], v=z[j+2];
        z[j]=f2add(u,v);
        z[j+2]=cmulf(f2sub(u,v), tw[k]);
    }
    {
        float2 w=tw[2*lane];
        float2 u=z[0],v=z[1];
        z[0]=f2add(u,v); z[1]=cmulf(f2sub(u,v),w);
        u=z[2]; v=z[3];
        z[2]=f2add(u,v); z[3]=cmulf(f2sub(u,v),w);
    }
    #pragma unroll
    for(int d=16; d>=1; d>>=1){
        int k=lane&(d-1);
        float2 w=tw[k*(64/d)];
        bool up=(lane&d)!=0;
        #pragma unroll
        for(int j=0;j<4;j++){
            float2 o=shflx(z[j],d);
            float2 r;
            if(up) r=cmulf(make_float2(o.x - z[j].x, o.y - z[j].y), w);
            else   r=make_float2(z[j].x+o.x, z[j].y+o.y);
            z[j]=r;
        }
    }
}

// DIT 128-pt FFT
template<bool CONJ>
DINLINE void fft128_dit(float2 z[4], const float2* tw, int lane){
    #pragma unroll
    for(int d=1; d<=16; d<<=1){
        int k=lane&(d-1);
        float2 w=tw[k*(64/d)];
        if(CONJ) w.y=-w.y;
        bool up=(lane&d)!=0;
        #pragma unroll
        for(int j=0;j<4;j++){
            float2 o=shflx(z[j],d);
            float2 r;
            if(up){
                float2 t=cmulf(w, z[j]);
                r=make_float2(o.x-t.x, o.y-t.y);
            } else {
                float2 t=cmulf(w, o);
                r=make_float2(z[j].x+t.x, z[j].y+t.y);
            }
            z[j]=r;
        }
    }
    {
        float2 w=tw[2*lane]; if(CONJ) w.y=-w.y;
        float2 t=cmulf(w,z[1]); float2 u=z[0];
        z[0]=f2add(u,t); z[1]=f2sub(u,t);
        t=cmulf(w,z[3]); u=z[2];
        z[2]=f2add(u,t); z[3]=f2sub(u,t);
    }
    #pragma unroll
    for(int j=0;j<2;j++){
        int k=j*32+lane;
        float2 w=tw[k]; if(CONJ) w.y=-w.y;
        float2 t=cmulf(w,z[j+2]); float2 u=z[j];
        z[j]=f2add(u,t);
        z[j+2]=f2sub(u,t);
    }
}

// ---------------- bicubic resize taps ----------------
DINLINE double cubicw(double t){
    t = fabs(t);
    const double a = -0.75;
    if(t <= 1.0) return ((a+2.0)*t - (a+3.0))*t*t + 1.0;
    if(t <  2.0) return a*(((t-5.0)*t+8.0)*t-4.0);
    return 0.0;
}
DINLINE void taps4(int j, int oldn, int newn, int* idx, float* wt){
    double s = (newn > 1) ? (double)j * (double)(oldn-1) / (double)(newn-1) : 0.0;
    int f = (int)floor(s);
    #pragma unroll
    for(int k=0;k<4;k++){
        int kk = f + k - 1;
        idx[k] = min(max(kk, 0), oldn-1);
        wt[k]  = (float)cubicw(s - (double)kk);
    }
}

__constant__ int c_SH[3]={16,8,24};
__constant__ int c_SW[3]={9,4,13};
__constant__ int c_RB[3]={0,16,24};

// ---------------- k_prep: zero stats + paired tf32 split of w1/spw ----------------
__global__ void __launch_bounds__(256) k_prep(const float* __restrict__ w1,
                                              const float* __restrict__ spw){
    int tid=blockIdx.x*256+threadIdx.x;
    if(blockIdx.x==0){
        for(int i=threadIdx.x;i<Bb*144;i+=256) g_stats[i]=0.f;
    }
    for(int i=tid;i<240*48;i+=256*16){
        int ncol=i/48, j=i%48;
        int kh=j/24, jj=j%24;
        int kt=jj/4, tig=jj%4;
        int k = kh*48 + kt*8 + tig;
        const float* src = (ncol<192)? (w1 + ncol*96) : (spw + (ncol-192)*96);
        float wa = src[k], wb = src[k+4];
        unsigned ha,la,hb,lb;
        tfsplit(wa,ha,la);
        tfsplit(wb,hb,lb);
        g_w1hp[i]=make_float2(__uint_as_float(ha), __uint_as_float(hb));
        g_w1lp[i]=make_float2(__uint_as_float(la), __uint_as_float(lb));
    }
}

// ---------------- k_filt1 ----------------
__global__ void __launch_bounds__(256) k_filt1(const float* __restrict__ cw0,
                                               const float* __restrict__ cw1,
                                               const float* __restrict__ cw2){
    __shared__ int   widx[65][4];
    __shared__ float wwt [65][4];
    __shared__ float2 rowb[13*Mm];
    int r = blockIdx.x;
    int s = (r<16)?0:((r<24)?1:2);
    int ih = r - c_RB[s];
    int ow = c_SW[s];
    const float* cws = (s==0)?cw0:((s==1)?cw1:cw2);
    int tid=threadIdx.x;
    if(tid<65) taps4(tid, ow, 65, widx[tid], wwt[tid]);
    const float2* src = (const float2*)(cws) + (size_t)ih*ow*Mm;
    for(int i=tid;i<ow*Mm;i+=256) rowb[i]=src[i];
    __syncthreads();
    float2* dst = g_tmp + (size_t)r*65*Mm;
    for(int e=tid;e<65*Mm;e+=256){
        int w=e/Mm, m=e%Mm;
        float ax=0.f, ay=0.f;
        #pragma unroll
        for(int a=0;a<4;a++){
            float wg=wwt[w][a];
            float2 v=rowb[widx[w][a]*Mm+m];
            ax+=wg*v.x; ay+=wg*v.y;
        }
        dst[e]=make_float2(ax,ay);
    }
}

// ---------------- k_filt2 ----------------
__global__ void __launch_bounds__(128) k_filt2(){
    __shared__ int   hidx[4];
    __shared__ float hwt [4];
    __shared__ float2 tile[48*65];
    int bid=blockIdx.x;
    int s  = bid/512;
    int rem= bid%512;
    int hq = rem/4;
    int m0 = (rem%4)*48;
    int tid=threadIdx.x;
    if(tid==0){
        int id[4]; float wt[4];
        taps4(hq, c_SH[s], 128, id, wt);
        #pragma unroll
        for(int a=0;a<4;a++){ hidx[a]=id[a]; hwt[a]=wt[a]; }
    }
    __syncthreads();
    const float2* base = g_tmp + (size_t)c_RB[s]*65*Mm;
    for(int e=tid;e<65*48;e+=128){
        int w=e/48, mm=e%48;
        int m=m0+mm;
        float ax=0.f, ay=0.f;
        #pragma unroll
        for(int a=0;a<4;a++){
            float2 v=base[(size_t)hidx[a]*65*Mm + w*Mm + m];
            ax+=hwt[a]*v.x; ay+=hwt[a]*v.y;
        }
        tile[mm*65+w]=make_float2(ax,ay);
    }
    __syncthreads();
    int hb=br7(hq);
    for(int e=tid;e<48*65;e+=128){
        int mm=e/65, w=e%65;
        g_filt[(size_t)(s*Mm+m0+mm)*SPEC + hb*65 + w]=tile[mm*65+w];
    }
}

// ---------------- k_pw1: tf32 MMA pwconv1+Soa + routing stats (paired B frags) ----------------
// smem floats: xs[128*100]=12800, whp[240*36 f2]=17280, wlp=17280,
//              sb[48*132]=6336, bnp[96], red[192]  => 53984 floats = 215.9 KB
#define P1_XS  0
#define P1_WH  (P1_XS+12800)
#define P1_WL  (P1_WH+17280)
#define P1_SB  (P1_WL+17280)
#define P1_BNP (P1_SB+6336)
#define P1_RED (P1_BNP+96)
#define P1_TOT (P1_RED+192)
__global__ void __launch_bounds__(256) k_pw1(const float* __restrict__ x,
                                             const float* __restrict__ s1,
                                             const float* __restrict__ b1,
                                             const float* __restrict__ bng,
                                             const float* __restrict__ bnb,
                                             const float* __restrict__ bnm,
                                             const float* __restrict__ bnv){
    float* S=(float*)SMEM;
    float* xs  = S+P1_XS;             // [128][100]
    float2* whp = (float2*)(S+P1_WH); // [240][36] float2 (data in [.][kt*4+tig], kt<6)
    float2* wlp = (float2*)(S+P1_WL);
    float* sb  = S+P1_SB;             // [48][132]
    float* bnp = S+P1_BNP;
    float* red = S+P1_RED;
    int tid=threadIdx.x;
    int b=blockIdx.y, pix0=blockIdx.x*128;
    const float* xb = x + ((size_t)b*16384 + pix0)*96;
    for(int i=tid;i<128*96;i+=256){ int p=i/96,c=i%96; xs[p*100+c]=xb[i]; }
    if(tid<48){
        float sc=rsqrtf(bnv[tid]+1e-5f)*bng[tid];
        bnp[tid]=sc;
        bnp[48+tid]=bnb[tid]-bnm[tid]*sc;
    }
    int warp=tid>>5, lane=tid&31;
    int gid=lane>>2, tig=lane&3;
    int pr0=warp*16;
    float C[30][4];
    #pragma unroll
    for(int n=0;n<30;n++){ C[n][0]=0.f;C[n][1]=0.f;C[n][2]=0.f;C[n][3]=0.f; }
    #pragma unroll 1
    for(int kh=0;kh<2;kh++){
        __syncthreads();
        for(int i=tid;i<240*24;i+=256){
            int ncol=i/24, j=i%24;
            whp[ncol*36+j]=g_w1hp[ncol*48 + kh*24 + j];
            wlp[ncol*36+j]=g_w1lp[ncol*48 + kh*24 + j];
        }
        __syncthreads();
        unsigned ah[6][4], al[6][4];
        #pragma unroll
        for(int kt=0;kt<6;kt++){
            int k0=kh*48+kt*8;
            float r0=xs[(pr0+gid  )*100 + k0+tig];
            float r1=xs[(pr0+gid+8)*100 + k0+tig];
            float r2=xs[(pr0+gid  )*100 + k0+tig+4];
            float r3=xs[(pr0+gid+8)*100 + k0+tig+4];
            tfsplit(r0,ah[kt][0],al[kt][0]);
            tfsplit(r1,ah[kt][1],al[kt][1]);
            tfsplit(r2,ah[kt][2],al[kt][2]);
            tfsplit(r3,ah[kt][3],al[kt][3]);
        }
        #pragma unroll
        for(int kt=0;kt<6;kt++){
            int fo=kt*4+tig;
            #pragma unroll
            for(int ng=0;ng<5;ng++){
                float2 bh[6], bl[6];
                #pragma unroll
                for(int u=0;u<6;u++){
                    int ncol=((ng*6+u)*8+gid);
                    bh[u]=whp[ncol*36+fo];
                    bl[u]=wlp[ncol*36+fo];
                }
                #pragma unroll
                for(int u=0;u<6;u++) mma8(C[ng*6+u], ah[kt], __float_as_uint(bh[u].x), __float_as_uint(bh[u].y));
                #pragma unroll
                for(int u=0;u<6;u++) mma8(C[ng*6+u], al[kt], __float_as_uint(bh[u].x), __float_as_uint(bh[u].y));
                #pragma unroll
                for(int u=0;u<6;u++) mma8(C[ng*6+u], ah[kt], __float_as_uint(bl[u].x), __float_as_uint(bl[u].y));
            }
        }
    }
    // gctx sums from xs BEFORE region reuse
    float gsum=0.f;
    if(tid<96){
        #pragma unroll 4
        for(int p=0;p<128;p++) gsum+=xs[p*100+tid];
    }
    // sctx rows -> sb
    #pragma unroll
    for(int n=24;n<30;n++){
        int sc=(n-24)*8+2*tig;
        int p=pr0+gid;
        sb[sc*132+p]      =C[n][0];
        sb[(sc+1)*132+p]  =C[n][1];
        sb[sc*132+p+8]    =C[n][2];
        sb[(sc+1)*132+p+8]=C[n][3];
    }
    float scb=*s1, bib=*b1;
    __syncthreads();
    // stage m<192 outputs (Soa applied) into outs[192][132]
    float* outs = S;   // 192*132 = 25344 floats, well inside region before sb
    #pragma unroll
    for(int n=0;n<24;n++){
        int mch=n*8+2*tig;
        int p=pr0+gid;
        float v0=fmaxf(C[n][0],0.f), v1=fmaxf(C[n][1],0.f);
        float v2=fmaxf(C[n][2],0.f), v3=fmaxf(C[n][3],0.f);
        outs[mch*132+p]      =scb*v0*v0+bib;
        outs[(mch+1)*132+p]  =scb*v1*v1+bib;
        outs[mch*132+p+8]    =scb*v2*v2+bib;
        outs[(mch+1)*132+p+8]=scb*v3*v3+bib;
    }
    if(tid<96) atomicAdd(&g_stats[b*144+tid], gsum);
    __syncthreads();
    float* op = g_xpre + (size_t)b*Mm*16384 + pix0;
    for(int i=tid;i<192*128;i+=256){
        int mm=i>>7, p=i&127;
        op[(size_t)mm*16384+p]=outs[mm*132+p];
    }
    if(tid<192){
        int sc=tid>>2, q=tid&3;
        float scale=bnp[sc], shift=bnp[48+sc];
        float s=0.f;
        #pragma unroll 4
        for(int p=q*32;p<q*32+32;p++) s+=fmaxf(sb[sc*132+p]*scale+shift,0.f);
        red[sc*4+q]=s;
    }
    __syncthreads();
    if(tid<48) atomicAdd(&g_stats[b*144+96+tid], red[4*tid]+red[4*tid+1]+red[4*tid+2]+red[4*tid+3]);
}

// ---------------- k_mlp ----------------
#define MLP_SF   0
#define MLP_FC1  (8*145)
#define MLP_HM   (MLP_FC1+36*145)
#define MLP_FC2  (MLP_HM+8*37)
#define MLP_TOT  (MLP_FC2+576*37)
__global__ void __launch_bounds__(512) k_mlp(const float* __restrict__ fc1,
                                             const float* __restrict__ fc2,
                                             const float* __restrict__ msc,
                                             const float* __restrict__ mbi){
    float* S=(float*)SMEM;
    float* sf  = S+MLP_SF;
    float* f1s = S+MLP_FC1;
    float* hm  = S+MLP_HM;
    float* f2s = S+MLP_FC2;
    int tid=threadIdx.x;
    for(int i=tid;i<8*144;i+=512){ int b=i/144,k=i%144; sf[b*145+k]=g_stats[i]*(1.f/16384.f); }
    for(int i=tid;i<36*144;i+=512){ int j=i/144,k=i%144; f1s[j*145+k]=fc1[i]; }
    for(int i=tid;i<576*36;i+=512){ int j=i/36,k=i%36; f2s[j*37+k]=fc2[i]; }
    __syncthreads();
    if(tid<288){
        int b=tid/36, j=tid%36;
        float a=0.f;
        #pragma unroll 8
        for(int k=0;k<144;k++) a+=sf[b*145+k]*f1s[j*145+k];
        float r=fmaxf(a,0.f);
        hm[b*37+j]=(*msc)*r*r + (*mbi);
    }
    __syncthreads();
    for(int idx=tid; idx<8*Mm; idx+=512){
        int b=idx/Mm, m=idx%Mm;
        float lg[3];
        #pragma unroll
        for(int s=0;s<3;s++){
            float a=0.f;
            const float* f2=f2s+(size_t)(s*Mm+m)*37;
            #pragma unroll
            for(int k=0;k<36;k++) a+=hm[b*37+k]*f2[k];
            lg[s]=a;
        }
        float mx=fmaxf(lg[0],fmaxf(lg[1],lg[2]));
        float e0=expf(lg[0]-mx), e1=expf(lg[1]-mx), e2=expf(lg[2]-mx);
        float inv=1.f/(e0+e1+e2);
        g_r[(b*3+0)*Mm+m]=e0*inv;
        g_r[(b*3+1)*Mm+m]=e1*inv;
        g_r[(b*3+2)*Mm+m]=e2*inv;
    }
}

// ---------------- k_fft (512 thr) ----------------
__global__ void __launch_bounds__(512) k_fft(){
    float2* sh=(float2*)SMEM;
    float2* sm = sh;
    float2* tmpAll = sh + SPEC;
    float2* tw = sh + SPEC + 2048;
    int tid=threadIdx.x, lane=tid&31, wid=tid>>5;
    int bm=blockIdx.x;
    int b=bm/Mm, m=bm%Mm;
    float* plane = g_xpre + (size_t)bm*16384;
    if(tid<64){
        float s,c;
        sincospif((float)tid*(1.0f/64.0f), &s, &c);
        tw[tid]=make_float2(c,-s);
    }
    __syncthreads();
    float2* tmp = tmpAll + wid*128;
    for(int pr=wid; pr<64; pr+=16){
        int ra=2*pr, rb=ra+1;
        float2 z[4];
        #pragma unroll
        for(int j=0;j<4;j++){
            int p=j*32+lane, q=br7(p);
            z[j]=make_float2(plane[ra*128+q], plane[rb*128+q]);
        }
        fft128_dit<false>(z,tw,lane);
        #pragma unroll
        for(int j=0;j<4;j++) tmp[j*32+lane]=z[j];
        __syncwarp();
        #pragma unroll
        for(int t=0;t<2;t++){
            int k=t*32+lane;
            float2 Zk=tmp[k], Zc=tmp[(128-k)&127];
            sm[ra*65+k]=make_float2(0.5f*(Zk.x+Zc.x), 0.5f*(Zk.y-Zc.y));
            sm[rb*65+k]=make_float2(0.5f*(Zk.y+Zc.y), 0.5f*(Zc.x-Zk.x));
        }
        if(lane==0){
            float2 Zk=tmp[64];
            sm[ra*65+64]=make_float2(Zk.x,0.f);
            sm[rb*65+64]=make_float2(Zk.y,0.f);
        }
        __syncwarp();
    }
    __syncthreads();
    for(int col=wid; col<65; col+=16){
        float2 z[4];
        #pragma unroll
        for(int j=0;j<4;j++) z[j]=sm[(j*32+lane)*65+col];
        fft128_dif(z,tw,lane);
        #pragma unroll
        for(int j=0;j<4;j++) sm[(j*32+lane)*65+col]=z[j];
    }
    __syncthreads();
    {
        float r0=g_r[(b*3+0)*Mm+m], r1=g_r[(b*3+1)*Mm+m], r2=g_r[(b*3+2)*Mm+m];
        const float2* f0=g_filt + (size_t)(0*Mm+m)*SPEC;
        const float2* f1=g_filt + (size_t)(1*Mm+m)*SPEC;
        const float2* f2=g_filt + (size_t)(2*Mm+m)*SPEC;
        for(int e=tid;e<SPEC;e+=512){
            float2 a=f0[e], bb=f1[e], c=f2[e];
            float2 comb=make_float2(a.x*r0+bb.x*r1+c.x*r2, a.y*r0+bb.y*r1+c.y*r2);
            sm[e]=cmulf(sm[e],comb);
        }
    }
    __syncthreads();
    for(int col=wid; col<65; col+=16){
        float2 z[4];
        #pragma unroll
        for(int j=0;j<4;j++) z[j]=sm[(j*32+lane)*65+col];
        fft128_dit<true>(z,tw,lane);
        #pragma unroll
        for(int j=0;j<4;j++) sm[(j*32+lane)*65+col]=z[j];
    }
    __syncthreads();
    for(int pr=wid; pr<64; pr+=16){
        int ra=2*pr, rb=ra+1;
        float2 z[4];
        #pragma unroll
        for(int j=0;j<4;j++){
            int p=j*32+lane, k=br7(p);
            float2 zz;
            if(k<=64){
                float2 a=sm[ra*65+k], bb=sm[rb*65+k];
                if(k==0||k==64){ a.y=0.f; bb.y=0.f; }
                zz=make_float2(a.x-bb.y, a.y+bb.x);
            } else {
                int kk=128-k;
                float2 a=sm[ra*65+kk], bb=sm[rb*65+kk];
                zz=make_float2(a.x+bb.y, bb.x-a.y);
            }
            z[j]=zz;
        }
        fft128_dit<true>(z,tw,lane);
        #pragma unroll
        for(int j=0;j<4;j++){
            int p=j*32+lane;
            plane[ra*128+p]=z[j].x*INV_HW;
            plane[rb*128+p]=z[j].y*INV_HW;
        }
    }
}

// ---------------- k_pw2 (512 thr, FFMA2, m-major weights) ----------------
#define PW2_AS   0
#define PW2_W2   (PW2_AS+24768)
#define PW2_TOT  (PW2_W2+192*98)
__global__ void __launch_bounds__(512) k_pw2(const float* __restrict__ w2,
                                             float* __restrict__ out){
    float* S=(float*)SMEM;
    float* As  = S+PW2_AS;     // [m][129]
    float* w2m = S+PW2_W2;     // [m][98] c-contiguous
    int tid=threadIdx.x;
    int b=blockIdx.y, pix0=blockIdx.x*128;
    const float* ap = g_xpre + (size_t)b*Mm*16384 + pix0;
    for(int i=tid;i<192*128;i+=512){
        int mm=i>>7, p=i&127;
        As[mm*129+p]=ap[(size_t)mm*16384+p];
    }
    for(int i=tid;i<96*192;i+=512){
        int c=i/192, m=i%192;
        w2m[m*98+c]=w2[i];
    }
    __syncthreads();
    int tx=tid&15, ty=tid>>4;
    const unsigned long long* w2p=(const unsigned long long*)w2m;   // [m][49]
    unsigned long long acc[4][3];
    #pragma unroll
    for(int i=0;i<4;i++)
        #pragma unroll
        for(int j=0;j<3;j++) acc[i][j]=0ull;
    for(int m=0;m<192;m++){
        unsigned long long xd[4], wv[3];
        #pragma unroll
        for(int i=0;i<4;i++) xd[i]=dup2(As[m*129 + ty+32*i]);
        #pragma unroll
        for(int j=0;j<3;j++) wv[j]=w2p[m*49 + tx+16*j];
        #pragma unroll
        for(int i=0;i<4;i++)
            #pragma unroll
            for(int j=0;j<3;j++) ffma2(acc[i][j], xd[i], wv[j]);
    }
    __syncthreads();
    float* outs=S;            // 128*97
    #pragma unroll
    for(int i=0;i<4;i++){
        int p=ty+32*i;
        #pragma unroll
        for(int j=0;j<3;j++){
            int c0=2*tx+32*j;
            float lo,hi;
            unpk2(acc[i][j], lo, hi);
            outs[p*97+c0]=lo;
            outs[p*97+c0+1]=hi;
        }
    }
    __syncthreads();
    float* op = out + ((size_t)b*16384 + pix0)*96;
    for(int i=tid;i<128*96;i+=512){
        int p=i/96, c=i%96;
        op[i]=outs[p*97+c];
    }
}

// ---------------- launch ----------------
extern "C" void kernel_launch(void* const* d_in, const int* in_sizes, int n_in,
                              void* d_out, int out_size){
    (void)in_sizes; (void)n_in; (void)out_size;
    const float* x   =(const float*)d_in[0];
    const float* w1  =(const float*)d_in[1];
    const float* s1  =(const float*)d_in[2];
    const float* b1  =(const float*)d_in[3];
    const float* cw0 =(const float*)d_in[4];
    const float* cw1 =(const float*)d_in[5];
    const float* cw2 =(const float*)d_in[6];
    const float* spw =(const float*)d_in[7];
    const float* bng =(const float*)d_in[8];
    const float* bnb =(const float*)d_in[9];
    const float* bnm =(const float*)d_in[10];
    const float* bnv =(const float*)d_in[11];
    const float* fc1 =(const float*)d_in[12];
    const float* msc =(const float*)d_in[13];
    const float* mbi =(const float*)d_in[14];
    const float* fc2 =(const float*)d_in[15];
    const float* w2  =(const float*)d_in[16];
    float* out=(float*)d_out;

    const int SM_PW1 = P1_TOT*4;                 // 215936 B
    const int SM_FFT = (SPEC+2048+64)*8;
    const int SM_PW2 = PW2_TOT*4;
    const int SM_MLP = MLP_TOT*4;

    cudaFuncSetAttribute(k_pw1, cudaFuncAttributeMaxDynamicSharedMemorySize, SM_PW1);
    cudaFuncSetAttribute(k_fft, cudaFuncAttributeMaxDynamicSharedMemorySize, SM_FFT);
    cudaFuncSetAttribute(k_pw2, cudaFuncAttributeMaxDynamicSharedMemorySize, SM_PW2);
    cudaFuncSetAttribute(k_mlp, cudaFuncAttributeMaxDynamicSharedMemorySize, SM_MLP);

    k_prep<<<16, 256>>>(w1, spw);
    k_filt1<<<48, 256>>>(cw0, cw1, cw2);
    k_filt2<<<3*128*4, 128>>>();
    k_pw1<<<dim3(128,Bb), 256, SM_PW1>>>(x, s1, b1, bng, bnb, bnm, bnv);
    k_mlp<<<1, 512, SM_MLP>>>(fc1, fc2, msc, mbi);
    k_fft<<<Bb*Mm, 512, SM_FFT>>>();
    k_pw2<<<dim3(128,Bb), 512, SM_PW2>>>(w2, out);
}

// round 15
// speedup vs baseline: 1.2045x; 1.0740x over previous
#include <cuda_runtime.h>
#include <math.h>

#define DINLINE __device__ __forceinline__

// ---------------- problem constants ----------------
#define Bb 8
#define Hh 128
#define Ww 128
#define Cc 96
#define Mm 192
#define SPEC (128*65)
#define INV_HW (1.0f/16384.0f)

// ---------------- device scratch ----------------
__device__ float  g_xpre[(size_t)Bb*Mm*Hh*Ww];     // reused in-place for xsp
__device__ float4 g_filt4[(size_t)3*Mm*SPEC/2];    // resized filters (BR h order), float4-aligned
__device__ float2 g_tmp[(size_t)48*65*Mm];         // separable-resize intermediate
__device__ float  g_r[Bb*3*Mm];
__device__ float  g_stats[Bb*144];
// paired tf32-split weights: [ncol][kh*24 + kt*4 + tig] = {v(k), v(k+4)}
__device__ float2 g_w1hp[240*48];
__device__ float2 g_w1lp[240*48];

extern __shared__ __align__(16) char SMEM[];

// ---------------- helpers ----------------
DINLINE int br7(int p){ return (int)(__brev((unsigned)p)>>25); }
DINLINE float2 cmulf(float2 a, float2 b){ return make_float2(a.x*b.x - a.y*b.y, a.x*b.y + a.y*b.x); }
DINLINE float2 f2add(float2 a,float2 b){ return make_float2(a.x+b.x, a.y+b.y); }
DINLINE float2 f2sub(float2 a,float2 b){ return make_float2(a.x-b.x, a.y-b.y); }
DINLINE float2 shflx(float2 v,int m){
    v.x = __shfl_xor_sync(0xffffffffu, v.x, m);
    v.y = __shfl_xor_sync(0xffffffffu, v.y, m);
    return v;
}
// tf32 helpers
DINLINE unsigned f2tf(float x){ unsigned r; asm("cvt.rna.tf32.f32 %0,%1;":"=r"(r):"f"(x)); return r; }
DINLINE void tfsplit(float x, unsigned& hi, unsigned& lo){
    hi = f2tf(x);
    lo = f2tf(x - __uint_as_float(hi));
}
DINLINE void mma8(float c[4], const unsigned a[4], unsigned b0, unsigned b1){
    asm("mma.sync.aligned.m16n8k8.row.col.f32.tf32.tf32.f32 "
        "{%0,%1,%2,%3},{%4,%5,%6,%7},{%8,%9},{%0,%1,%2,%3};"
        : "+f"(c[0]),"+f"(c[1]),"+f"(c[2]),"+f"(c[3])
        : "r"(a[0]),"r"(a[1]),"r"(a[2]),"r"(a[3]),"r"(b0),"r"(b1));
}
// packed f32x2 FMA (Blackwell)
DINLINE unsigned long long dup2(float x){
    unsigned long long r;
    asm("mov.b64 %0,{%1,%1};":"=l"(r):"f"(x));
    return r;
}
DINLINE void ffma2(unsigned long long& d, unsigned long long a, unsigned long long b){
    asm("fma.rn.f32x2 %0,%1,%2,%3;":"=l"(d):"l"(a),"l"(b),"l"(d));
}
DINLINE void unpk2(unsigned long long v, float& lo, float& hi){
    asm("mov.b64 {%0,%1},%2;":"=f"(lo),"=f"(hi):"l"(v));
}

// Forward DIF 128-pt FFT
DINLINE void fft128_dif(float2 z[4], const float2* tw, int lane){
    #pragma unroll
    for(int j=0;j<2;j++){
        int k=j*32+lane;
        float2 u=z[j], v=z[j+2];
        z[j]=f2add(u,v);
        z[j+2]=cmulf(f2sub(u,v), tw[k]);
    }
    {
        float2 w=tw[2*lane];
        float2 u=z[0],v=z[1];
        z[0]=f2add(u,v); z[1]=cmulf(f2sub(u,v),w);
        u=z[2]; v=z[3];
        z[2]=f2add(u,v); z[3]=cmulf(f2sub(u,v),w);
    }
    #pragma unroll
    for(int d=16; d>=1; d>>=1){
        int k=lane&(d-1);
        float2 w=tw[k*(64/d)];
        bool up=(lane&d)!=0;
        #pragma unroll
        for(int j=0;j<4;j++){
            float2 o=shflx(z[j],d);
            float2 r;
            if(up) r=cmulf(make_float2(o.x - z[j].x, o.y - z[j].y), w);
            else   r=make_float2(z[j].x+o.x, z[j].y+o.y);
            z[j]=r;
        }
    }
}

// DIT 128-pt FFT
template<bool CONJ>
DINLINE void fft128_dit(float2 z[4], const float2* tw, int lane){
    #pragma unroll
    for(int d=1; d<=16; d<<=1){
        int k=lane&(d-1);
        float2 w=tw[k*(64/d)];
        if(CONJ) w.y=-w.y;
        bool up=(lane&d)!=0;
        #pragma unroll
        for(int j=0;j<4;j++){
            float2 o=shflx(z[j],d);
            float2 r;
            if(up){
                float2 t=cmulf(w, z[j]);
                r=make_float2(o.x-t.x, o.y-t.y);
            } else {
                float2 t=cmulf(w, o);
                r=make_float2(z[j].x+t.x, z[j].y+t.y);
            }
            z[j]=r;
        }
    }
    {
        float2 w=tw[2*lane]; if(CONJ) w.y=-w.y;
        float2 t=cmulf(w,z[1]); float2 u=z[0];
        z[0]=f2add(u,t); z[1]=f2sub(u,t);
        t=cmulf(w,z[3]); u=z[2];
        z[2]=f2add(u,t); z[3]=f2sub(u,t);
    }
    #pragma unroll
    for(int j=0;j<2;j++){
        int k=j*32+lane;
        float2 w=tw[k]; if(CONJ) w.y=-w.y;
        float2 t=cmulf(w,z[j+2]); float2 u=z[j];
        z[j]=f2add(u,t);
        z[j+2]=f2sub(u,t);
    }
}

// ---------------- bicubic resize taps ----------------
DINLINE double cubicw(double t){
    t = fabs(t);
    const double a = -0.75;
    if(t <= 1.0) return ((a+2.0)*t - (a+3.0))*t*t + 1.0;
    if(t <  2.0) return a*(((t-5.0)*t+8.0)*t-4.0);
    return 0.0;
}
DINLINE void taps4(int j, int oldn, int newn, int* idx, float* wt){
    double s = (newn > 1) ? (double)j * (double)(oldn-1) / (double)(newn-1) : 0.0;
    int f = (int)floor(s);
    #pragma unroll
    for(int k=0;k<4;k++){
        int kk = f + k - 1;
        idx[k] = min(max(kk, 0), oldn-1);
        wt[k]  = (float)cubicw(s - (double)kk);
    }
}

__constant__ int c_SH[3]={16,8,24};
__constant__ int c_SW[3]={9,4,13};
__constant__ int c_RB[3]={0,16,24};

// ---------------- k_prep: zero stats + paired tf32 split of w1/spw ----------------
__global__ void __launch_bounds__(256) k_prep(const float* __restrict__ w1,
                                              const float* __restrict__ spw){
    int tid=blockIdx.x*256+threadIdx.x;
    if(blockIdx.x==0){
        for(int i=threadIdx.x;i<Bb*144;i+=256) g_stats[i]=0.f;
    }
    for(int i=tid;i<240*48;i+=256*16){
        int ncol=i/48, j=i%48;
        int kh=j/24, jj=j%24;
        int kt=jj/4, tig=jj%4;
        int k = kh*48 + kt*8 + tig;
        const float* src = (ncol<192)? (w1 + ncol*96) : (spw + (ncol-192)*96);
        float wa = src[k], wb = src[k+4];
        unsigned ha,la,hb,lb;
        tfsplit(wa,ha,la);
        tfsplit(wb,hb,lb);
        g_w1hp[i]=make_float2(__uint_as_float(ha), __uint_as_float(hb));
        g_w1lp[i]=make_float2(__uint_as_float(la), __uint_as_float(lb));
    }
}

// ---------------- k_filt1 ----------------
__global__ void __launch_bounds__(256) k_filt1(const float* __restrict__ cw0,
                                               const float* __restrict__ cw1,
                                               const float* __restrict__ cw2){
    __shared__ int   widx[65][4];
    __shared__ float wwt [65][4];
    __shared__ float2 rowb[13*Mm];
    int r = blockIdx.x;
    int s = (r<16)?0:((r<24)?1:2);
    int ih = r - c_RB[s];
    int ow = c_SW[s];
    const float* cws = (s==0)?cw0:((s==1)?cw1:cw2);
    int tid=threadIdx.x;
    if(tid<65) taps4(tid, ow, 65, widx[tid], wwt[tid]);
    const float2* src = (const float2*)(cws) + (size_t)ih*ow*Mm;
    for(int i=tid;i<ow*Mm;i+=256) rowb[i]=src[i];
    __syncthreads();
    float2* dst = g_tmp + (size_t)r*65*Mm;
    for(int e=tid;e<65*Mm;e+=256){
        int w=e/Mm, m=e%Mm;
        float ax=0.f, ay=0.f;
        #pragma unroll
        for(int a=0;a<4;a++){
            float wg=wwt[w][a];
            float2 v=rowb[widx[w][a]*Mm+m];
            ax+=wg*v.x; ay+=wg*v.y;
        }
        dst[e]=make_float2(ax,ay);
    }
}

// ---------------- k_filt2 ----------------
__global__ void __launch_bounds__(128) k_filt2(){
    __shared__ int   hidx[4];
    __shared__ float hwt [4];
    __shared__ float2 tile[48*65];
    int bid=blockIdx.x;
    int s  = bid/512;
    int rem= bid%512;
    int hq = rem/4;
    int m0 = (rem%4)*48;
    int tid=threadIdx.x;
    if(tid==0){
        int id[4]; float wt[4];
        taps4(hq, c_SH[s], 128, id, wt);
        #pragma unroll
        for(int a=0;a<4;a++){ hidx[a]=id[a]; hwt[a]=wt[a]; }
    }
    __syncthreads();
    const float2* base = g_tmp + (size_t)c_RB[s]*65*Mm;
    for(int e=tid;e<65*48;e+=128){
        int w=e/48, mm=e%48;
        int m=m0+mm;
        float ax=0.f, ay=0.f;
        #pragma unroll
        for(int a=0;a<4;a++){
            float2 v=base[(size_t)hidx[a]*65*Mm + w*Mm + m];
            ax+=hwt[a]*v.x; ay+=hwt[a]*v.y;
        }
        tile[mm*65+w]=make_float2(ax,ay);
    }
    __syncthreads();
    int hb=br7(hq);
    float2* gf2=(float2*)g_filt4;
    for(int e=tid;e<48*65;e+=128){
        int mm=e/65, w=e%65;
        gf2[(size_t)(s*Mm+m0+mm)*SPEC + hb*65 + w]=tile[mm*65+w];
    }
}

// ---------------- k_pw1: tf32 MMA pwconv1+Soa + routing stats (paired B frags) ----------------
#define P1_XS  0
#define P1_WH  (P1_XS+12800)
#define P1_WL  (P1_WH+17280)
#define P1_SB  (P1_WL+17280)
#define P1_BNP (P1_SB+6336)
#define P1_RED (P1_BNP+96)
#define P1_TOT (P1_RED+192)
__global__ void __launch_bounds__(256) k_pw1(const float* __restrict__ x,
                                             const float* __restrict__ s1,
                                             const float* __restrict__ b1,
                                             const float* __restrict__ bng,
                                             const float* __restrict__ bnb,
                                             const float* __restrict__ bnm,
                                             const float* __restrict__ bnv){
    float* S=(float*)SMEM;
    float* xs  = S+P1_XS;             // [128][100]
    float2* whp = (float2*)(S+P1_WH); // [240][36] float2
    float2* wlp = (float2*)(S+P1_WL);
    float* sb  = S+P1_SB;             // [48][132]
    float* bnp = S+P1_BNP;
    float* red = S+P1_RED;
    int tid=threadIdx.x;
    int b=blockIdx.y, pix0=blockIdx.x*128;
    const float* xb = x + ((size_t)b*16384 + pix0)*96;
    for(int i=tid;i<128*96;i+=256){ int p=i/96,c=i%96; xs[p*100+c]=xb[i]; }
    if(tid<48){
        float sc=rsqrtf(bnv[tid]+1e-5f)*bng[tid];
        bnp[tid]=sc;
        bnp[48+tid]=bnb[tid]-bnm[tid]*sc;
    }
    int warp=tid>>5, lane=tid&31;
    int gid=lane>>2, tig=lane&3;
    int pr0=warp*16;
    float C[30][4];
    #pragma unroll
    for(int n=0;n<30;n++){ C[n][0]=0.f;C[n][1]=0.f;C[n][2]=0.f;C[n][3]=0.f; }
    #pragma unroll 1
    for(int kh=0;kh<2;kh++){
        __syncthreads();
        for(int i=tid;i<240*24;i+=256){
            int ncol=i/24, j=i%24;
            whp[ncol*36+j]=g_w1hp[ncol*48 + kh*24 + j];
            wlp[ncol*36+j]=g_w1lp[ncol*48 + kh*24 + j];
        }
        __syncthreads();
        unsigned ah[6][4], al[6][4];
        #pragma unroll
        for(int kt=0;kt<6;kt++){
            int k0=kh*48+kt*8;
            float r0=xs[(pr0+gid  )*100 + k0+tig];
            float r1=xs[(pr0+gid+8)*100 + k0+tig];
            float r2=xs[(pr0+gid  )*100 + k0+tig+4];
            float r3=xs[(pr0+gid+8)*100 + k0+tig+4];
            tfsplit(r0,ah[kt][0],al[kt][0]);
            tfsplit(r1,ah[kt][1],al[kt][1]);
            tfsplit(r2,ah[kt][2],al[kt][2]);
            tfsplit(r3,ah[kt][3],al[kt][3]);
        }
        #pragma unroll
        for(int kt=0;kt<6;kt++){
            int fo=kt*4+tig;
            #pragma unroll
            for(int ng=0;ng<5;ng++){
                float2 bh[6], bl[6];
                #pragma unroll
                for(int u=0;u<6;u++){
                    int ncol=((ng*6+u)*8+gid);
                    bh[u]=whp[ncol*36+fo];
                    bl[u]=wlp[ncol*36+fo];
                }
                #pragma unroll
                for(int u=0;u<6;u++) mma8(C[ng*6+u], ah[kt], __float_as_uint(bh[u].x), __float_as_uint(bh[u].y));
                #pragma unroll
                for(int u=0;u<6;u++) mma8(C[ng*6+u], al[kt], __float_as_uint(bh[u].x), __float_as_uint(bh[u].y));
                #pragma unroll
                for(int u=0;u<6;u++) mma8(C[ng*6+u], ah[kt], __float_as_uint(bl[u].x), __float_as_uint(bl[u].y));
            }
        }
    }
    float gsum=0.f;
    if(tid<96){
        #pragma unroll 4
        for(int p=0;p<128;p++) gsum+=xs[p*100+tid];
    }
    #pragma unroll
    for(int n=24;n<30;n++){
        int sc=(n-24)*8+2*tig;
        int p=pr0+gid;
        sb[sc*132+p]      =C[n][0];
        sb[(sc+1)*132+p]  =C[n][1];
        sb[sc*132+p+8]    =C[n][2];
        sb[(sc+1)*132+p+8]=C[n][3];
    }
    float scb=*s1, bib=*b1;
    __syncthreads();
    float* outs = S;
    #pragma unroll
    for(int n=0;n<24;n++){
        int mch=n*8+2*tig;
        int p=pr0+gid;
        float v0=fmaxf(C[n][0],0.f), v1=fmaxf(C[n][1],0.f);
        float v2=fmaxf(C[n][2],0.f), v3=fmaxf(C[n][3],0.f);
        outs[mch*132+p]      =scb*v0*v0+bib;
        outs[(mch+1)*132+p]  =scb*v1*v1+bib;
        outs[mch*132+p+8]    =scb*v2*v2+bib;
        outs[(mch+1)*132+p+8]=scb*v3*v3+bib;
    }
    if(tid<96) atomicAdd(&g_stats[b*144+tid], gsum);
    __syncthreads();
    float* op = g_xpre + (size_t)b*Mm*16384 + pix0;
    for(int i=tid;i<192*128;i+=256){
        int mm=i>>7, p=i&127;
        op[(size_t)mm*16384+p]=outs[mm*132+p];
    }
    if(tid<192){
        int sc=tid>>2, q=tid&3;
        float scale=bnp[sc], shift=bnp[48+sc];
        float s=0.f;
        #pragma unroll 4
        for(int p=q*32;p<q*32+32;p++) s+=fmaxf(sb[sc*132+p]*scale+shift,0.f);
        red[sc*4+q]=s;
    }
    __syncthreads();
    if(tid<48) atomicAdd(&g_stats[b*144+96+tid], red[4*tid]+red[4*tid+1]+red[4*tid+2]+red[4*tid+3]);
}

// ---------------- k_mlp ----------------
#define MLP_SF   0
#define MLP_FC1  (8*145)
#define MLP_HM   (MLP_FC1+36*145)
#define MLP_FC2  (MLP_HM+8*37)
#define MLP_TOT  (MLP_FC2+576*37)
__global__ void __launch_bounds__(512) k_mlp(const float* __restrict__ fc1,
                                             const float* __restrict__ fc2,
                                             const float* __restrict__ msc,
                                             const float* __restrict__ mbi){
    float* S=(float*)SMEM;
    float* sf  = S+MLP_SF;
    float* f1s = S+MLP_FC1;
    float* hm  = S+MLP_HM;
    float* f2s = S+MLP_FC2;
    int tid=threadIdx.x;
    for(int i=tid;i<8*144;i+=512){ int b=i/144,k=i%144; sf[b*145+k]=g_stats[i]*(1.f/16384.f); }
    for(int i=tid;i<36*144;i+=512){ int j=i/144,k=i%144; f1s[j*145+k]=fc1[i]; }
    for(int i=tid;i<576*36;i+=512){ int j=i/36,k=i%36; f2s[j*37+k]=fc2[i]; }
    __syncthreads();
    if(tid<288){
        int b=tid/36, j=tid%36;
        float a=0.f;
        #pragma unroll 8
        for(int k=0;k<144;k++) a+=sf[b*145+k]*f1s[j*145+k];
        float r=fmaxf(a,0.f);
        hm[b*37+j]=(*msc)*r*r + (*mbi);
    }
    __syncthreads();
    for(int idx=tid; idx<8*Mm; idx+=512){
        int b=idx/Mm, m=idx%Mm;
        float lg[3];
        #pragma unroll
        for(int s=0;s<3;s++){
            float a=0.f;
            const float* f2=f2s+(size_t)(s*Mm+m)*37;
            #pragma unroll
            for(int k=0;k<36;k++) a+=hm[b*37+k]*f2[k];
            lg[s]=a;
        }
        float mx=fmaxf(lg[0],fmaxf(lg[1],lg[2]));
        float e0=expf(lg[0]-mx), e1=expf(lg[1]-mx), e2=expf(lg[2]-mx);
        float inv=1.f/(e0+e1+e2);
        g_r[(b*3+0)*Mm+m]=e0*inv;
        g_r[(b*3+1)*Mm+m]=e1*inv;
        g_r[(b*3+2)*Mm+m]=e2*inv;
    }
}

// ---------------- k_fft (512 thr) ----------------
__global__ void __launch_bounds__(512) k_fft(){
    float2* sh=(float2*)SMEM;
    float2* sm = sh;
    float2* tmpAll = sh + SPEC;
    float2* tw = sh + SPEC + 2048;
    int tid=threadIdx.x, lane=tid&31, wid=tid>>5;
    int bm=blockIdx.x;
    int b=bm/Mm, m=bm%Mm;
    float* plane = g_xpre + (size_t)bm*16384;
    if(tid<64){
        float s,c;
        sincospif((float)tid*(1.0f/64.0f), &s, &c);
        tw[tid]=make_float2(c,-s);
    }
    __syncthreads();
    float2* tmp = tmpAll + wid*128;
    for(int pr=wid; pr<64; pr+=16){
        int ra=2*pr, rb=ra+1;
        float2 z[4];
        #pragma unroll
        for(int j=0;j<4;j++){
            int p=j*32+lane, q=br7(p);
            z[j]=make_float2(plane[ra*128+q], plane[rb*128+q]);
        }
        fft128_dit<false>(z,tw,lane);
        #pragma unroll
        for(int j=0;j<4;j++) tmp[j*32+lane]=z[j];
        __syncwarp();
        #pragma unroll
        for(int t=0;t<2;t++){
            int k=t*32+lane;
            float2 Zk=tmp[k], Zc=tmp[(128-k)&127];
            sm[ra*65+k]=make_float2(0.5f*(Zk.x+Zc.x), 0.5f*(Zk.y-Zc.y));
            sm[rb*65+k]=make_float2(0.5f*(Zk.y+Zc.y), 0.5f*(Zc.x-Zk.x));
        }
        if(lane==0){
            float2 Zk=tmp[64];
            sm[ra*65+64]=make_float2(Zk.x,0.f);
            sm[rb*65+64]=make_float2(Zk.y,0.f);
        }
        __syncwarp();
    }
    __syncthreads();
    for(int col=wid; col<65; col+=16){
        float2 z[4];
        #pragma unroll
        for(int j=0;j<4;j++) z[j]=sm[(j*32+lane)*65+col];
        fft128_dif(z,tw,lane);
        #pragma unroll
        for(int j=0;j<4;j++) sm[(j*32+lane)*65+col]=z[j];
    }
    __syncthreads();
    // Phase C: routed filter multiply, float4 (2 spec elems per iter)
    {
        float r0=g_r[(b*3+0)*Mm+m], r1=g_r[(b*3+1)*Mm+m], r2=g_r[(b*3+2)*Mm+m];
        const float4* f0=g_filt4 + (size_t)(0*Mm+m)*(SPEC/2);
        const float4* f1=g_filt4 + (size_t)(1*Mm+m)*(SPEC/2);
        const float4* f2=g_filt4 + (size_t)(2*Mm+m)*(SPEC/2);
        float4* sm4=(float4*)sm;
        for(int e=tid;e<SPEC/2;e+=512){
            float4 a=f0[e], bb=f1[e], c=f2[e];
            float2 cb0=make_float2(a.x*r0+bb.x*r1+c.x*r2, a.y*r0+bb.y*r1+c.y*r2);
            float2 cb1=make_float2(a.z*r0+bb.z*r1+c.z*r2, a.w*r0+bb.w*r1+c.w*r2);
            float4 v=sm4[e];
            float2 u0=cmulf(make_float2(v.x,v.y), cb0);
            float2 u1=cmulf(make_float2(v.z,v.w), cb1);
            sm4[e]=make_float4(u0.x,u0.y,u1.x,u1.y);
        }
    }
    __syncthreads();
    for(int col=wid; col<65; col+=16){
        float2 z[4];
        #pragma unroll
        for(int j=0;j<4;j++) z[j]=sm[(j*32+lane)*65+col];
        fft128_dit<true>(z,tw,lane);
        #pragma unroll
        for(int j=0;j<4;j++) sm[(j*32+lane)*65+col]=z[j];
    }
    __syncthreads();
    for(int pr=wid; pr<64; pr+=16){
        int ra=2*pr, rb=ra+1;
        float2 z[4];
        #pragma unroll
        for(int j=0;j<4;j++){
            int p=j*32+lane, k=br7(p);
            float2 zz;
            if(k<=64){
                float2 a=sm[ra*65+k], bb=sm[rb*65+k];
                if(k==0||k==64){ a.y=0.f; bb.y=0.f; }
                zz=make_float2(a.x-bb.y, a.y+bb.x);
            } else {
                int kk=128-k;
                float2 a=sm[ra*65+kk], bb=sm[rb*65+kk];
                zz=make_float2(a.x+bb.y, bb.x-a.y);
            }
            z[j]=zz;
        }
        fft128_dit<true>(z,tw,lane);
        #pragma unroll
        for(int j=0;j<4;j++){
            int p=j*32+lane;
            plane[ra*128+p]=z[j].x*INV_HW;
            plane[rb*128+p]=z[j].y*INV_HW;
        }
    }
}

// ---------------- k_pw2 (512 thr, FFMA2, K-chunked for 2 blocks/SM) ----------------
// smem per chunk: As[96][129]=12384, w2m[96][98]=9408 => 21792 floats = 87.2 KB
#define PW2_AS   0
#define PW2_W2   (PW2_AS+96*129)
#define PW2_TOT  (PW2_W2+96*98)
__global__ void __launch_bounds__(512) k_pw2(const float* __restrict__ w2,
                                             float* __restrict__ out){
    float* S=(float*)SMEM;
    float* As  = S+PW2_AS;     // [96][129] per chunk
    float* w2m = S+PW2_W2;     // [96][98] c-contiguous per chunk
    int tid=threadIdx.x;
    int b=blockIdx.y, pix0=blockIdx.x*128;
    int tx=tid&15, ty=tid>>4;
    const unsigned long long* w2p=(const unsigned long long*)w2m;   // [mloc][49]
    unsigned long long acc[4][3];
    #pragma unroll
    for(int i=0;i<4;i++)
        #pragma unroll
        for(int j=0;j<3;j++) acc[i][j]=0ull;
    #pragma unroll 1
    for(int mc=0;mc<2;mc++){
        __syncthreads();
        const float* ap = g_xpre + ((size_t)b*Mm + mc*96)*16384 + pix0;
        for(int i=tid;i<96*128;i+=512){
            int mm=i>>7, p=i&127;
            As[mm*129+p]=ap[(size_t)mm*16384+p];
        }
        for(int i=tid;i<96*96;i+=512){
            int c=i/96, mloc=i%96;
            w2m[mloc*98+c]=w2[c*192 + mc*96 + mloc];
        }
        __syncthreads();
        for(int mloc=0;mloc<96;mloc++){
            unsigned long long xd[4], wv[3];
            #pragma unroll
            for(int i=0;i<4;i++) xd[i]=dup2(As[mloc*129 + ty+32*i]);
            #pragma unroll
            for(int j=0;j<3;j++) wv[j]=w2p[mloc*49 + tx+16*j];
            #pragma unroll
            for(int i=0;i<4;i++)
                #pragma unroll
                for(int j=0;j<3;j++) ffma2(acc[i][j], xd[i], wv[j]);
        }
    }
    __syncthreads();
    float* outs=S;            // 128*97 = 12416 < 21792
    #pragma unroll
    for(int i=0;i<4;i++){
        int p=ty+32*i;
        #pragma unroll
        for(int j=0;j<3;j++){
            int c0=2*tx+32*j;
            float lo,hi;
            unpk2(acc[i][j], lo, hi);
            outs[p*97+c0]=lo;
            outs[p*97+c0+1]=hi;
        }
    }
    __syncthreads();
    float* op = out + ((size_t)b*16384 + pix0)*96;
    for(int i=tid;i<128*96;i+=512){
        int p=i/96, c=i%96;
        op[i]=outs[p*97+c];
    }
}

// ---------------- launch ----------------
extern "C" void kernel_launch(void* const* d_in, const int* in_sizes, int n_in,
                              void* d_out, int out_size){
    (void)in_sizes; (void)n_in; (void)out_size;
    const float* x   =(const float*)d_in[0];
    const float* w1  =(const float*)d_in[1];
    const float* s1  =(const float*)d_in[2];
    const float* b1  =(const float*)d_in[3];
    const float* cw0 =(const float*)d_in[4];
    const float* cw1 =(const float*)d_in[5];
    const float* cw2 =(const float*)d_in[6];
    const float* spw =(const float*)d_in[7];
    const float* bng =(const float*)d_in[8];
    const float* bnb =(const float*)d_in[9];
    const float* bnm =(const float*)d_in[10];
    const float* bnv =(const float*)d_in[11];
    const float* fc1 =(const float*)d_in[12];
    const float* msc =(const float*)d_in[13];
    const float* mbi =(const float*)d_in[14];
    const float* fc2 =(const float*)d_in[15];
    const float* w2  =(const float*)d_in[16];
    float* out=(float*)d_out;

    const int SM_PW1 = P1_TOT*4;                 // 215936 B
    const int SM_FFT = (SPEC+2048+64)*8;
    const int SM_PW2 = PW2_TOT*4;                // 87168 B
    const int SM_MLP = MLP_TOT*4;

    cudaFuncSetAttribute(k_pw1, cudaFuncAttributeMaxDynamicSharedMemorySize, SM_PW1);
    cudaFuncSetAttribute(k_fft, cudaFuncAttributeMaxDynamicSharedMemorySize, SM_FFT);
    cudaFuncSetAttribute(k_pw2, cudaFuncAttributeMaxDynamicSharedMemorySize, SM_PW2);
    cudaFuncSetAttribute(k_mlp, cudaFuncAttributeMaxDynamicSharedMemorySize, SM_MLP);

    k_prep<<<16, 256>>>(w1, spw);
    k_filt1<<<48, 256>>>(cw0, cw1, cw2);
    k_filt2<<<3*128*4, 128>>>();
    k_pw1<<<dim3(128,Bb), 256, SM_PW1>>>(x, s1, b1, bng, bnb, bnm, bnv);
    k_mlp<<<1, 512, SM_MLP>>>(fc1, fc2, msc, mbi);
    k_fft<<<Bb*Mm, 512, SM_FFT>>>();
    k_pw2<<<dim3(128,Bb), 512, SM_PW2>>>(w2, out);
}